// round 13
// baseline (speedup 1.0000x reference)
#include <cuda_runtime.h>
#include <cuda_fp16.h>
#include <mma.h>
#include <math.h>
#include <stdint.h>

using namespace nvcuda;

#define BB 512
#define AA 4
#define EE 10
#define HH 256
#define TT 10
#define MP_ROWS (BB*AA*EE)   // 20480
#define MA_ROWS (BB*AA)      // 2048
#define G3H (3*HH)           // 768

// ---------------- scratch ----------------
__device__ __half g_h_hi[2][MP_ROWS * HH];
__device__ __half g_h_lo[2][MP_ROWS * HH];
__device__ __half g_xcat_hi[2][MA_ROWS * 512];   // [feat | ma]
__device__ __half g_xcat_lo[2][MA_ROWS * 512];
__device__ __half g_proc_hi[MP_ROWS * HH];
__device__ __half g_t1_hi[MA_ROWS * HH];
__device__ float g_t2[MA_ROWS * HH];
__device__ float g_xp8[MP_ROWS * 8];     // [ob0,ob1,ph0,ph1,ph2,0,0,0]
__device__ float g_xa4[MA_ROWS * 4];     // [g0,g1,g2,0]
__device__ float g_Wp8[G3H * 8];         // [w0..w4, bih, bhh, 0]
__device__ float g_Wa8[G3H * 8];         // [wg0..2, bih, bhh, 0,0,0]
__device__ __half g_Whhp[G3H * HH];
__device__ __half g_Wfcp[HH * HH];
__device__ __half g_Wcat[1024 * 512];
__device__ __half g_Wfca[HH * HH];
__device__ __half g_Wm1[HH * HH];

// ---------------- helpers ----------------
__device__ __forceinline__ float fsig(float x) {
    float e = __expf(-x);
    return __fdividef(1.0f, 1.0f + e);
}
__device__ __forceinline__ float ftanh_(float x) {
    float xc = fmaxf(fminf(x, 15.0f), -15.0f);
    float e = __expf(-2.0f * xc);
    return __fdividef(1.0f - e, 1.0f + e);
}
__device__ __forceinline__ float eluf_(float x) { return x > 0.0f ? x : expm1f(x); }
__device__ __forceinline__ void split_fp16(float x, __half& hi, __half& lo) {
    hi = __float2half_rn(x);
    lo = __float2half_rn(x - __half2float(hi));
}
__device__ __forceinline__ void cp16(void* dst, const void* src) {
    unsigned d = (unsigned)__cvta_generic_to_shared(dst);
    asm volatile("cp.async.cg.shared.global [%0], [%1], 16;\n" :: "r"(d), "l"(src));
}
__device__ __forceinline__ void cp_commit() { asm volatile("cp.async.commit_group;\n" ::); }
template<int N> __device__ __forceinline__ void cp_wait() { asm volatile("cp.async.wait_group %0;\n" :: "n"(N)); }

// ---------------- prep kernels ----------------
__global__ void prep_xp_kernel(const float* __restrict__ obs, const float* __restrict__ phys,
                               float* __restrict__ xp8)
{
    int r = blockIdx.x * blockDim.x + threadIdx.x;
    if (r >= MP_ROWS) return;
    int b = r / (AA*EE);
    int e = r % EE;
    float* o = xp8 + r * 8;
    o[0] = obs[r*2+0]; o[1] = obs[r*2+1];
    const float* ph = phys + (b * EE + e) * 3;
    o[2] = ph[0]; o[3] = ph[1]; o[4] = ph[2];
    o[5] = 0.f; o[6] = 0.f; o[7] = 0.f;
}
__global__ void prep_wp8_kernel(const float* __restrict__ Wih, const float* __restrict__ bih,
                                const float* __restrict__ bhh, float* __restrict__ Wp8)
{
    int r = blockIdx.x * blockDim.x + threadIdx.x;
    if (r >= G3H) return;
    float* o = Wp8 + r * 8;
#pragma unroll
    for (int k = 0; k < 5; k++) o[k] = Wih[r*5+k];
    o[5] = bih[r]; o[6] = bhh[r]; o[7] = 0.f;
}
__global__ void prep_xa_kernel(const float* __restrict__ goals, float* __restrict__ xa4)
{
    int m = blockIdx.x * blockDim.x + threadIdx.x;
    if (m >= MA_ROWS) return;
    float* o = xa4 + m * 4;
    o[0] = goals[m*3+0]; o[1] = goals[m*3+1]; o[2] = goals[m*3+2]; o[3] = 0.f;
}
__global__ void prep_wa8_kernel(const float* __restrict__ Wih, const float* __restrict__ bih,
                                const float* __restrict__ bhh, float* __restrict__ Wa8)
{
    int r = blockIdx.x * blockDim.x + threadIdx.x;
    if (r >= G3H) return;
    float* o = Wa8 + r * 8;
    o[0] = Wih[r*259+256]; o[1] = Wih[r*259+257]; o[2] = Wih[r*259+258];
    o[3] = bih[r]; o[4] = bhh[r]; o[5] = 0.f; o[6] = 0.f; o[7] = 0.f;
}
__global__ void split_kernel(const float* __restrict__ src,
                             __half* __restrict__ hi, __half* __restrict__ lo, int n)
{
    int i = blockIdx.x * blockDim.x + threadIdx.x;
    if (i >= n) return;
    split_fp16(src[i], hi[i], lo[i]);
}
__global__ void split_strided_kernel(const float* __restrict__ src,
                                     __half* __restrict__ hi, __half* __restrict__ lo,
                                     int rows, int cols, int ldo)
{
    int i = blockIdx.x * blockDim.x + threadIdx.x;
    if (i >= rows * cols) return;
    int r = i / cols, c = i - r * cols;
    split_fp16(src[i], hi[r * ldo + c], lo[r * ldo + c]);
}
__global__ void conv_kernel(const float* __restrict__ src, __half* __restrict__ dst, int n)
{
    int i = blockIdx.x * blockDim.x + threadIdx.x;
    if (i >= n) return;
    dst[i] = __float2half_rn(src[i]);
}
// Wcat [1024, 512]: rows g*256+n. g=0:[Wih_r|Whh_r] g=1:[Wih_z|Whh_z] g=2:[Wih_n|0] g=3:[0|Whh_n]
__global__ void build_wcat_kernel(const float* __restrict__ Wih,  // [768,259]
                                  const float* __restrict__ Whh,  // [768,256]
                                  __half* __restrict__ Wcat)
{
    int idx = blockIdx.x * blockDim.x + threadIdx.x;
    if (idx >= 1024 * 512) return;
    int row = idx >> 9, col = idx & 511;
    int g = row >> 8, n = row & 255;
    float v = 0.0f;
    if (g < 2) {
        v = (col < 256) ? Wih[(g * 256 + n) * 259 + col] : Whh[(g * 256 + n) * 256 + (col - 256)];
    } else if (g == 2) {
        if (col < 256) v = Wih[(512 + n) * 259 + col];
    } else {
        if (col >= 256) v = Whh[(512 + n) * 256 + (col - 256)];
    }
    Wcat[idx] = __float2half_rn(v);
}

// ---------------- fused fp16 single-pass GEMM kernel (BK=64) ----------------
// MODE 0: physical GRU  (NSEG=3 gate slices, K=256)
// MODE 1: action GRU    (NSEG=4, K=512; segs 2/3 half-dead -> skipped exactly)
// MODE 2: ELU layer     (NSEG=NSEGP contiguous 64-col blocks, K=256)
template<int MODE, int BM, int NSEGP>
__global__ __launch_bounds__(256) void fused_kernel(
    const __half* __restrict__ Ahi, int lda,
    const __half* __restrict__ B,
    const float* __restrict__ xw,     // xp8 / xa4 / bias
    const float* __restrict__ swg,    // Wp8 / Wa8 / unused
    const __half* __restrict__ oldHi, const __half* __restrict__ oldLo, int oldLd,
    __half* __restrict__ Ohi, __half* __restrict__ Olo, int ldo,
    float* __restrict__ Ofp)
{
    constexpr int NSEG = (MODE == 0) ? 3 : ((MODE == 1) ? 4 : NSEGP);
    constexpr int K = (MODE == 1) ? 512 : 256;
    constexpr int KT = K / 64;
    constexpr int MI = BM / 64;
    constexpr int STR = 72;
    constexpr int AITER = BM / 32;
    constexpr int AHS = BM * STR;
    constexpr int BHS = NSEG * 64 * STR;

    extern __shared__ __align__(16) char smem_raw[];
    __half* sm = (__half*)smem_raw;
    __half* sAh[2] = { sm,           sm + AHS };
    __half* sB[2]  = { sm + 2*AHS,   sm + 2*AHS + BHS };

    const int m0 = blockIdx.x * BM;
    const int n0 = blockIdx.y * ((MODE == 2) ? NSEG * 64 : 64);
    const int tid = threadIdx.x;
    const int wid = tid >> 5;
    const int lane = tid & 31;
    const int wm = wid >> 1, wn = wid & 1;

    auto load_tile = [&](int s, int kt) {
        const int k0 = kt * 64;
#pragma unroll
        for (int r = 0; r < AITER; r++) {
            int c = tid + r * 256;
            int row = c >> 3, kk = (c & 7) * 8;
            cp16(sAh[s] + row * STR + kk, Ahi + (size_t)(m0 + row) * lda + k0 + kk);
        }
#pragma unroll
        for (int r = 0; r < NSEG * 2; r++) {
            int c = tid + r * 256;
            int srow = c >> 3, kk = (c & 7) * 8;
            if (MODE == 1) {
                int seg = srow >> 6;
                if ((seg == 2 && kt >= 4) || (seg == 3 && kt < 4)) continue;
            }
            int srcrow = (MODE == 2) ? (n0 + srow) : ((srow >> 6) * 256 + n0 + (srow & 63));
            cp16(sB[s] + srow * STR + kk, B + (size_t)srcrow * K + k0 + kk);
        }
    };

    wmma::fragment<wmma::accumulator, 16, 16, 16, float> acc[NSEG][MI][2];
#pragma unroll
    for (int g = 0; g < NSEG; g++)
#pragma unroll
        for (int i = 0; i < MI; i++)
#pragma unroll
            for (int j = 0; j < 2; j++) wmma::fill_fragment(acc[g][i][j], 0.0f);

    load_tile(0, 0); cp_commit();
    if (KT > 1) { load_tile(1, 1); cp_commit(); }

    for (int kt = 0; kt < KT; kt++) {
        if (kt == KT - 1) cp_wait<0>(); else cp_wait<1>();
        __syncthreads();
        const int s = kt & 1;
        const bool featHalf = (MODE != 1) || (kt < 4);
#pragma unroll
        for (int kc = 0; kc < 64; kc += 16) {
            wmma::fragment<wmma::matrix_a, 16, 16, 16, __half, wmma::row_major> ah[MI];
#pragma unroll
            for (int i = 0; i < MI; i++)
                wmma::load_matrix_sync(ah[i], sAh[s] + (wm * 16 * MI + i * 16) * STR + kc, STR);
#pragma unroll
            for (int g = 0; g < NSEG; g++) {
                if (MODE == 1) {
                    if ((g == 2 && !featHalf) || (g == 3 && featHalf)) continue;
                }
                wmma::fragment<wmma::matrix_b, 16, 16, 16, __half, wmma::col_major> b[2];
#pragma unroll
                for (int j = 0; j < 2; j++)
                    wmma::load_matrix_sync(b[j], sB[s] + (g * 64 + wn * 32 + j * 16) * STR + kc, STR);
#pragma unroll
                for (int i = 0; i < MI; i++)
#pragma unroll
                    for (int j = 0; j < 2; j++)
                        wmma::mma_sync(acc[g][i][j], ah[i], b[j], acc[g][i][j]);
            }
        }
        __syncthreads();
        if (kt + 2 < KT) { load_tile(kt & 1, kt + 2); cp_commit(); }
    }

    // ---------------- epilogue ----------------
    float* wbuf = (float*)smem_raw;
    float* sX = wbuf + 8 * NSEG * 320;
    constexpr int XW = (MODE == 1) ? 4 : 8;
    float* sW = sX + BM * XW;

    if (MODE != 2) {
#pragma unroll
        for (int r = 0; r < (BM * XW + 255) / 256; r++) {
            int c = tid + r * 256;
            if (c < BM * XW) sX[c] = xw[(size_t)(m0 + (c / XW)) * XW + (c % XW)];
        }
#pragma unroll
        for (int r = 0; r < 6; r++) {
            int c = tid + r * 256;
            int srow = c >> 3, k = c & 7;
            sW[c] = swg[(size_t)((srow >> 6) * 256 + n0 + (srow & 63)) * 8 + k];
        }
    }
    __syncthreads();

    float* wb = wbuf + wid * NSEG * 320;
    const int r_ = lane >> 1;
    const int c0_ = (lane & 1) * 8;

#pragma unroll
    for (int i = 0; i < MI; i++) {
#pragma unroll
        for (int j = 0; j < 2; j++) {
#pragma unroll
            for (int g = 0; g < NSEG; g++)
                wmma::store_matrix_sync(wb + g * 320, acc[g][i][j], 20, wmma::mem_row_major);
            __syncwarp();

            const int mloc = wm * 16 * MI + i * 16 + r_;
            const int m = m0 + mloc;
            const int nl0 = wn * 32 + j * 16 + c0_;

            __half oh8[8], ol8[8];

            if (MODE == 2) {
#pragma unroll
                for (int g = 0; g < NSEG; g++) {
                    const int nabs = n0 + g * 64 + nl0;
                    float4 b0 = *(const float4*)&xw[nabs];
                    float4 b1 = *(const float4*)&xw[nabs + 4];
                    float bia[8] = {b0.x,b0.y,b0.z,b0.w,b1.x,b1.y,b1.z,b1.w};
                    float ov[8];
#pragma unroll
                    for (int cc = 0; cc < 8; cc++) {
                        float v = eluf_(wb[g * 320 + r_ * 20 + c0_ + cc] + bia[cc]);
                        ov[cc] = v;
                        oh8[cc] = __float2half_rn(v);
                    }
                    if (Ofp) {
                        *(float4*)&Ofp[(size_t)m * 256 + nabs] = make_float4(ov[0],ov[1],ov[2],ov[3]);
                        *(float4*)&Ofp[(size_t)m * 256 + nabs + 4] = make_float4(ov[4],ov[5],ov[6],ov[7]);
                    }
                    if (Ohi) {
                        *(uint4*)&Ohi[(size_t)m * ldo + nabs] = *(uint4*)oh8;
                    }
                }
            } else {
                const int nabs = n0 + nl0;
                uint4 hv4 = *(const uint4*)&oldHi[(size_t)m * oldLd + nabs];
                uint4 lv4 = *(const uint4*)&oldLo[(size_t)m * oldLd + nabs];
                const __half* hvp = (const __half*)&hv4;
                const __half* lvp = (const __half*)&lv4;
                float xr[XW];
#pragma unroll
                for (int k = 0; k < XW; k++) xr[k] = sX[mloc * XW + k];
#pragma unroll
                for (int cc = 0; cc < 8; cc++) {
                    int nl = nl0 + cc;
                    const float* w0 = sW + (0 * 64 + nl) * 8;
                    const float* w1 = sW + (1 * 64 + nl) * 8;
                    const float* w2 = sW + (2 * 64 + nl) * 8;
                    float a0 = wb[0 * 320 + r_ * 20 + c0_ + cc];
                    float a1 = wb[1 * 320 + r_ * 20 + c0_ + cc];
                    float a2 = wb[2 * 320 + r_ * 20 + c0_ + cc];
                    float gi_r, gi_z, gi_n, rr, zz, nn;
                    if (MODE == 0) {
                        gi_r = w0[5]; gi_z = w1[5]; gi_n = w2[5];
#pragma unroll
                        for (int k = 0; k < 5; k++) {
                            gi_r += xr[k] * w0[k];
                            gi_z += xr[k] * w1[k];
                            gi_n += xr[k] * w2[k];
                        }
                        rr = fsig(gi_r + a0 + w0[6]);
                        zz = fsig(gi_z + a1 + w1[6]);
                        nn = ftanh_(gi_n + rr * (a2 + w2[6]));
                    } else {
                        float a3 = wb[3 * 320 + r_ * 20 + c0_ + cc];
                        gi_r = w0[3]; gi_z = w1[3]; gi_n = w2[3];
#pragma unroll
                        for (int k = 0; k < 3; k++) {
                            gi_r += xr[k] * w0[k];
                            gi_z += xr[k] * w1[k];
                            gi_n += xr[k] * w2[k];
                        }
                        rr = fsig(gi_r + a0 + w0[4]);
                        zz = fsig(gi_z + a1 + w1[4]);
                        nn = ftanh_(gi_n + a2 + rr * (a3 + w2[4]));
                    }
                    float hold = __half2float(hvp[cc]) + __half2float(lvp[cc]);
                    float hnew = (1.0f - zz) * nn + zz * hold;
                    split_fp16(hnew, oh8[cc], ol8[cc]);
                }
                *(uint4*)&Ohi[(size_t)m * ldo + nabs] = *(uint4*)oh8;
                *(uint4*)&Olo[(size_t)m * ldo + nabs] = *(uint4*)ol8;
            }
            __syncwarp();
        }
    }
}

// ---------------- entity max-pool (hi planes only) ----------------
__global__ void pool_kernel(const __half* __restrict__ phi,
                            __half* __restrict__ xcat_hi)
{
    int idx = blockIdx.x * blockDim.x + threadIdx.x;
    if (idx >= MA_ROWS * 32) return;
    int m = idx >> 5, c8 = (idx & 31) * 8;
    float v[8];
#pragma unroll
    for (int k = 0; k < 8; k++) v[k] = -1e30f;
#pragma unroll
    for (int e = 0; e < EE; e++) {
        size_t off = (size_t)(m * EE + e) * HH + c8;
        uint4 h4 = *(const uint4*)&phi[off];
        const __half* hp = (const __half*)&h4;
#pragma unroll
        for (int k = 0; k < 8; k++)
            v[k] = fmaxf(v[k], __half2float(hp[k]));
    }
    __half h8[8];
#pragma unroll
    for (int k = 0; k < 8; k++) h8[k] = __float2half_rn(v[k]);
    *(uint4*)&xcat_hi[(size_t)m * 512 + c8] = *(uint4*)h8;
}

// ---------------- head ----------------
__global__ void head_kernel(const float* __restrict__ t2,
                            const float* __restrict__ Wm2, const float* __restrict__ bm2,
                            float* __restrict__ out, int tstep)
{
    int warp = (blockIdx.x * blockDim.x + threadIdx.x) >> 5;
    int lane = threadIdx.x & 31;
    if (warp >= MA_ROWS) return;
    float s0 = 0.0f, s1 = 0.0f;
    for (int k = lane; k < HH; k += 32) {
        float x = t2[warp * HH + k];
        s0 += x * Wm2[k];
        s1 += x * Wm2[HH + k];
    }
#pragma unroll
    for (int off = 16; off; off >>= 1) {
        s0 += __shfl_xor_sync(0xffffffffu, s0, off);
        s1 += __shfl_xor_sync(0xffffffffu, s1, off);
    }
    if (lane == 0) {
        out[((size_t)tstep * MA_ROWS + warp) * 2 + 0] = ftanh_(s0 + bm2[0]) * 0.05f;
        out[((size_t)tstep * MA_ROWS + warp) * 2 + 1] = ftanh_(s1 + bm2[1]) * 0.05f;
    }
}

// ---------------- host launcher ----------------
extern "C" void kernel_launch(void* const* d_in, const int* in_sizes, int n_in,
                              void* d_out, int out_size)
{
    const float* obs    = (const float*)d_in[0];
    const float* phys   = (const float*)d_in[1];
    const float* goals  = (const float*)d_in[2];
    const float* mem_p  = (const float*)d_in[3];
    const float* mem_a  = (const float*)d_in[4];
    const float* Wih_p  = (const float*)d_in[5];
    const float* Whh_p  = (const float*)d_in[6];
    const float* bih_p  = (const float*)d_in[7];
    const float* bhh_p  = (const float*)d_in[8];
    const float* Wfc_p  = (const float*)d_in[9];
    const float* bfc_p  = (const float*)d_in[10];
    const float* Wih_a  = (const float*)d_in[11];
    const float* Whh_a  = (const float*)d_in[12];
    const float* bih_a  = (const float*)d_in[13];
    const float* bhh_a  = (const float*)d_in[14];
    const float* Wfc_a  = (const float*)d_in[15];
    const float* bfc_a  = (const float*)d_in[16];
    const float* Wm1    = (const float*)d_in[17];
    const float* bm1    = (const float*)d_in[18];
    const float* Wm2    = (const float*)d_in[19];
    const float* bm2    = (const float*)d_in[20];
    float* out = (float*)d_out;

    void* p;
    __half *h_hi[2], *h_lo[2], *xc_hi[2], *xc_lo[2];
    cudaGetSymbolAddress(&p, g_h_hi);    h_hi[0] = (__half*)p; h_hi[1] = h_hi[0] + (size_t)MP_ROWS*HH;
    cudaGetSymbolAddress(&p, g_h_lo);    h_lo[0] = (__half*)p; h_lo[1] = h_lo[0] + (size_t)MP_ROWS*HH;
    cudaGetSymbolAddress(&p, g_xcat_hi); xc_hi[0] = (__half*)p; xc_hi[1] = xc_hi[0] + (size_t)MA_ROWS*512;
    cudaGetSymbolAddress(&p, g_xcat_lo); xc_lo[0] = (__half*)p; xc_lo[1] = xc_lo[0] + (size_t)MA_ROWS*512;
    cudaGetSymbolAddress(&p, g_proc_hi); __half* proc_hi = (__half*)p;
    cudaGetSymbolAddress(&p, g_t1_hi);   __half* t1_hi = (__half*)p;
    cudaGetSymbolAddress(&p, g_t2);      float* t2 = (float*)p;
    cudaGetSymbolAddress(&p, g_xp8);     float* xp8 = (float*)p;
    cudaGetSymbolAddress(&p, g_xa4);     float* xa4 = (float*)p;
    cudaGetSymbolAddress(&p, g_Wp8);     float* Wp8 = (float*)p;
    cudaGetSymbolAddress(&p, g_Wa8);     float* Wa8 = (float*)p;
    cudaGetSymbolAddress(&p, g_Whhp);    __half* Whhp = (__half*)p;
    cudaGetSymbolAddress(&p, g_Wfcp);    __half* Wfcp = (__half*)p;
    cudaGetSymbolAddress(&p, g_Wcat);    __half* Wcat = (__half*)p;
    cudaGetSymbolAddress(&p, g_Wfca);    __half* Wfca = (__half*)p;
    cudaGetSymbolAddress(&p, g_Wm1);     __half* Wm1h = (__half*)p;

    const int SM_0 = (2*128*72 + 2*3*64*72) * 2;   // 92160
    const int SM_1 = (2*64*72  + 2*4*64*72) * 2;   // 92160
    const int SM_2 = (2*128*72 + 2*2*64*72) * 2;   // 73728
    cudaFuncSetAttribute((const void*)fused_kernel<0,128,1>, cudaFuncAttributeMaxDynamicSharedMemorySize, SM_0);
    cudaFuncSetAttribute((const void*)fused_kernel<1,64,1>,  cudaFuncAttributeMaxDynamicSharedMemorySize, SM_1);
    cudaFuncSetAttribute((const void*)fused_kernel<2,128,2>, cudaFuncAttributeMaxDynamicSharedMemorySize, SM_2);

    // ---- one-time stream/event setup ----
    static cudaStream_t sA = nullptr, sB = nullptr;
    static cudaEvent_t evFork = nullptr, evJoinA = nullptr, evJoinB = nullptr;
    static cudaEvent_t evG[TT], evF[TT], evP[TT], evA[TT];
    if (sA == nullptr) {
        cudaStreamCreateWithFlags(&sA, cudaStreamNonBlocking);
        cudaStreamCreateWithFlags(&sB, cudaStreamNonBlocking);
        cudaEventCreateWithFlags(&evFork, cudaEventDisableTiming);
        cudaEventCreateWithFlags(&evJoinA, cudaEventDisableTiming);
        cudaEventCreateWithFlags(&evJoinB, cudaEventDisableTiming);
        for (int i = 0; i < TT; i++) {
            cudaEventCreateWithFlags(&evG[i], cudaEventDisableTiming);
            cudaEventCreateWithFlags(&evF[i], cudaEventDisableTiming);
            cudaEventCreateWithFlags(&evP[i], cudaEventDisableTiming);
            cudaEventCreateWithFlags(&evA[i], cudaEventDisableTiming);
        }
    }

    cudaStream_t s0 = 0;

    // ---- fork sB immediately so its prep work is rooted in the capture ----
    cudaEventRecord(evFork, s0);
    cudaStreamWaitEvent(sB, evFork, 0);

    // ---- gru_p-critical prep on s0 ----
    split_kernel<<<(MP_ROWS*HH + 255)/256, 256, 0, s0>>>(mem_p, h_hi[0], h_lo[0], MP_ROWS*HH);
    conv_kernel<<<(G3H*HH + 255)/256, 256, 0, s0>>>(Whh_p, Whhp, G3H*HH);
    prep_xp_kernel<<<(MP_ROWS + 255)/256, 256, 0, s0>>>(obs, phys, xp8);
    prep_wp8_kernel<<<(G3H + 255)/256, 256, 0, s0>>>(Wih_p, bih_p, bhh_p, Wp8);

    // ---- everything else on sB (hides under gru_p(0)) ----
    split_strided_kernel<<<(MA_ROWS*HH + 255)/256, 256, 0, sB>>>(mem_a, xc_hi[0] + 256, xc_lo[0] + 256, MA_ROWS, HH, 512);
    conv_kernel<<<(HH*HH + 255)/256, 256, 0, sB>>>(Wfc_p, Wfcp, HH*HH);
    conv_kernel<<<(HH*HH + 255)/256, 256, 0, sB>>>(Wfc_a, Wfca, HH*HH);
    conv_kernel<<<(HH*HH + 255)/256, 256, 0, sB>>>(Wm1, Wm1h, HH*HH);
    build_wcat_kernel<<<(1024*512 + 255)/256, 256, 0, sB>>>(Wih_a, Whh_a, Wcat);
    prep_xa_kernel<<<(MA_ROWS + 255)/256, 256, 0, sB>>>(goals, xa4);
    prep_wa8_kernel<<<(G3H + 255)/256, 256, 0, sB>>>(Wih_a, bih_a, bhh_a, Wa8);

    // ---- recurrence ----
    // s0 : gru_p chain (critical path). sB : fc_p + pool. sA : action chain.
    int cur = 0;
    for (int t = 0; t < TT; t++) {
        int nxt = cur ^ 1;
        // ---- physical GRU on s0 ----
        if (t >= 2) cudaStreamWaitEvent(s0, evF[t - 2], 0);
        fused_kernel<0,128,1><<<dim3(MP_ROWS/128, 4), 256, SM_0, s0>>>(
            h_hi[cur], HH, Whhp, xp8, Wp8,
            h_hi[cur], h_lo[cur], HH,
            h_hi[nxt], h_lo[nxt], HH, nullptr);
        cudaEventRecord(evG[t], s0);

        // ---- fc_p + pool on sB ----
        cudaStreamWaitEvent(sB, evG[t], 0);
        fused_kernel<2,128,2><<<dim3(MP_ROWS/128, 2), 256, SM_2, sB>>>(
            h_hi[nxt], HH, Wfcp, bfc_p, nullptr,
            nullptr, nullptr, 0,
            proc_hi, nullptr, HH, nullptr);
        cudaEventRecord(evF[t], sB);
        if (t >= 2) cudaStreamWaitEvent(sB, evA[t - 2], 0);
        pool_kernel<<<(MA_ROWS*32 + 255)/256, 256, 0, sB>>>(proc_hi, xc_hi[cur]);
        cudaEventRecord(evP[t], sB);

        // ---- action chain on sA ----
        cudaStreamWaitEvent(sA, evP[t], 0);
        fused_kernel<1,64,1><<<dim3(MA_ROWS/64, 4), 256, SM_1, sA>>>(
            xc_hi[cur], 512, Wcat, xa4, Wa8,
            xc_hi[cur] + 256, xc_lo[cur] + 256, 512,
            xc_hi[nxt] + 256, xc_lo[nxt] + 256, 512, nullptr);
        cudaEventRecord(evA[t], sA);
        fused_kernel<2,128,2><<<dim3(MA_ROWS/128, 2), 256, SM_2, sA>>>(
            xc_hi[nxt] + 256, 512, Wfca, bfc_a, nullptr,
            nullptr, nullptr, 0,
            t1_hi, nullptr, HH, nullptr);
        fused_kernel<2,128,2><<<dim3(MA_ROWS/128, 2), 256, SM_2, sA>>>(
            t1_hi, HH, Wm1h, bm1, nullptr,
            nullptr, nullptr, 0,
            nullptr, nullptr, 0, t2);
        head_kernel<<<(MA_ROWS*32 + 255)/256, 256, 0, sA>>>(t2, Wm2, bm2, out, t);
        cur = nxt;
    }

    // join side streams back into stream 0
    cudaEventRecord(evJoinA, sA);
    cudaStreamWaitEvent(s0, evJoinA, 0);
    cudaEventRecord(evJoinB, sB);
    cudaStreamWaitEvent(s0, evJoinB, 0);
}

// round 14
// speedup vs baseline: 1.1166x; 1.1166x over previous
#include <cuda_runtime.h>
#include <cuda_fp16.h>
#include <mma.h>
#include <math.h>
#include <stdint.h>

using namespace nvcuda;

#define BB 512
#define AA 4
#define EE 10
#define HH 256
#define TT 10
#define MP_ROWS (BB*AA*EE)   // 20480
#define MA_ROWS (BB*AA)      // 2048
#define G3H (3*HH)           // 768

// ---------------- scratch ----------------
__device__ __half g_h_hi[3][MP_ROWS * HH];
__device__ __half g_h_lo[3][MP_ROWS * HH];
__device__ __half g_xcat_hi[2][MA_ROWS * 512];   // [feat | ma]
__device__ __half g_xcat_lo[2][MA_ROWS * 512];
__device__ __half g_proc_hi[MP_ROWS * HH];
__device__ __half g_t1_hi[MA_ROWS * HH];
__device__ float g_t2[MA_ROWS * HH];
__device__ float g_xp8[MP_ROWS * 8];     // [ob0,ob1,ph0,ph1,ph2,0,0,0]
__device__ float g_xa4[MA_ROWS * 4];     // [g0,g1,g2,0]
__device__ float g_Wp8[G3H * 8];         // [w0..w4, bih, bhh, 0]
__device__ float g_Wa8[G3H * 8];         // [wg0..2, bih, bhh, 0,0,0]
__device__ __half g_Whhp[G3H * HH];
__device__ __half g_Wfcp[HH * HH];
__device__ __half g_Wcat[1024 * 512];
__device__ __half g_Wfca[HH * HH];
__device__ __half g_Wm1[HH * HH];

// ---------------- helpers ----------------
__device__ __forceinline__ float fsig(float x) {
    float e = __expf(-x);
    return __fdividef(1.0f, 1.0f + e);
}
__device__ __forceinline__ float ftanh_(float x) {
    float xc = fmaxf(fminf(x, 15.0f), -15.0f);
    float e = __expf(-2.0f * xc);
    return __fdividef(1.0f - e, 1.0f + e);
}
__device__ __forceinline__ float eluf_(float x) { return x > 0.0f ? x : expm1f(x); }
__device__ __forceinline__ void split_fp16(float x, __half& hi, __half& lo) {
    hi = __float2half_rn(x);
    lo = __float2half_rn(x - __half2float(hi));
}
__device__ __forceinline__ void cp16(void* dst, const void* src) {
    unsigned d = (unsigned)__cvta_generic_to_shared(dst);
    asm volatile("cp.async.cg.shared.global [%0], [%1], 16;\n" :: "r"(d), "l"(src));
}
__device__ __forceinline__ void cp_commit() { asm volatile("cp.async.commit_group;\n" ::); }
template<int N> __device__ __forceinline__ void cp_wait() { asm volatile("cp.async.wait_group %0;\n" :: "n"(N)); }

// ---------------- prep kernels ----------------
__global__ void prep_xp_kernel(const float* __restrict__ obs, const float* __restrict__ phys,
                               float* __restrict__ xp8)
{
    int r = blockIdx.x * blockDim.x + threadIdx.x;
    if (r >= MP_ROWS) return;
    int b = r / (AA*EE);
    int e = r % EE;
    float* o = xp8 + r * 8;
    o[0] = obs[r*2+0]; o[1] = obs[r*2+1];
    const float* ph = phys + (b * EE + e) * 3;
    o[2] = ph[0]; o[3] = ph[1]; o[4] = ph[2];
    o[5] = 0.f; o[6] = 0.f; o[7] = 0.f;
}
__global__ void prep_wp8_kernel(const float* __restrict__ Wih, const float* __restrict__ bih,
                                const float* __restrict__ bhh, float* __restrict__ Wp8)
{
    int r = blockIdx.x * blockDim.x + threadIdx.x;
    if (r >= G3H) return;
    float* o = Wp8 + r * 8;
#pragma unroll
    for (int k = 0; k < 5; k++) o[k] = Wih[r*5+k];
    o[5] = bih[r]; o[6] = bhh[r]; o[7] = 0.f;
}
__global__ void prep_xa_kernel(const float* __restrict__ goals, float* __restrict__ xa4)
{
    int m = blockIdx.x * blockDim.x + threadIdx.x;
    if (m >= MA_ROWS) return;
    float* o = xa4 + m * 4;
    o[0] = goals[m*3+0]; o[1] = goals[m*3+1]; o[2] = goals[m*3+2]; o[3] = 0.f;
}
__global__ void prep_wa8_kernel(const float* __restrict__ Wih, const float* __restrict__ bih,
                                const float* __restrict__ bhh, float* __restrict__ Wa8)
{
    int r = blockIdx.x * blockDim.x + threadIdx.x;
    if (r >= G3H) return;
    float* o = Wa8 + r * 8;
    o[0] = Wih[r*259+256]; o[1] = Wih[r*259+257]; o[2] = Wih[r*259+258];
    o[3] = bih[r]; o[4] = bhh[r]; o[5] = 0.f; o[6] = 0.f; o[7] = 0.f;
}
__global__ void split_kernel(const float* __restrict__ src,
                             __half* __restrict__ hi, __half* __restrict__ lo, int n)
{
    int i = blockIdx.x * blockDim.x + threadIdx.x;
    if (i >= n) return;
    split_fp16(src[i], hi[i], lo[i]);
}
__global__ void split_strided_kernel(const float* __restrict__ src,
                                     __half* __restrict__ hi, __half* __restrict__ lo,
                                     int rows, int cols, int ldo)
{
    int i = blockIdx.x * blockDim.x + threadIdx.x;
    if (i >= rows * cols) return;
    int r = i / cols, c = i - r * cols;
    split_fp16(src[i], hi[r * ldo + c], lo[r * ldo + c]);
}
__global__ void conv_kernel(const float* __restrict__ src, __half* __restrict__ dst, int n)
{
    int i = blockIdx.x * blockDim.x + threadIdx.x;
    if (i >= n) return;
    dst[i] = __float2half_rn(src[i]);
}
// Wcat [1024, 512]: rows g*256+n. g=0:[Wih_r|Whh_r] g=1:[Wih_z|Whh_z] g=2:[Wih_n|0] g=3:[0|Whh_n]
__global__ void build_wcat_kernel(const float* __restrict__ Wih,  // [768,259]
                                  const float* __restrict__ Whh,  // [768,256]
                                  __half* __restrict__ Wcat)
{
    int idx = blockIdx.x * blockDim.x + threadIdx.x;
    if (idx >= 1024 * 512) return;
    int row = idx >> 9, col = idx & 511;
    int g = row >> 8, n = row & 255;
    float v = 0.0f;
    if (g < 2) {
        v = (col < 256) ? Wih[(g * 256 + n) * 259 + col] : Whh[(g * 256 + n) * 256 + (col - 256)];
    } else if (g == 2) {
        if (col < 256) v = Wih[(512 + n) * 259 + col];
    } else {
        if (col >= 256) v = Whh[(512 + n) * 256 + (col - 256)];
    }
    Wcat[idx] = __float2half_rn(v);
}

// ---------------- fused fp16 single-pass GEMM kernel (BK=64) ----------------
// MODE 0: physical GRU  (NSEG=3, K=256), MODE 1: action GRU (NSEG=4, K=512),
// MODE 2: ELU layer     (NSEG=1, K=256).
// MODE 1 sparsity: seg 2 (n_i) is zero for K>=256, seg 3 (n_h) zero for K<256;
// their MMAs and B-loads are skipped in the dead half (exact).
template<int MODE, int BM>
__global__ __launch_bounds__(256) void fused_kernel(
    const __half* __restrict__ Ahi, int lda,
    const __half* __restrict__ B,
    const float* __restrict__ xw,     // xp8 / xa4 / bias
    const float* __restrict__ swg,    // Wp8 / Wa8 / unused
    const __half* __restrict__ oldHi, const __half* __restrict__ oldLo, int oldLd,
    __half* __restrict__ Ohi, __half* __restrict__ Olo, int ldo,
    float* __restrict__ Ofp)
{
    constexpr int NSEG = (MODE == 0) ? 3 : ((MODE == 1) ? 4 : 1);
    constexpr int K = (MODE == 1) ? 512 : 256;
    constexpr int KT = K / 64;
    constexpr int MI = BM / 64;
    constexpr int STR = 72;
    constexpr int AITER = BM / 32;
    constexpr int AHS = BM * STR;
    constexpr int BHS = NSEG * 64 * STR;

    extern __shared__ __align__(16) char smem_raw[];
    __half* sm = (__half*)smem_raw;
    __half* sAh[2] = { sm,           sm + AHS };
    __half* sB[2]  = { sm + 2*AHS,   sm + 2*AHS + BHS };

    const int m0 = blockIdx.x * BM;
    const int n0 = blockIdx.y * 64;
    const int tid = threadIdx.x;
    const int wid = tid >> 5;
    const int lane = tid & 31;
    const int wm = wid >> 1, wn = wid & 1;

    auto load_tile = [&](int s, int kt) {
        const int k0 = kt * 64;
#pragma unroll
        for (int r = 0; r < AITER; r++) {
            int c = tid + r * 256;
            int row = c >> 3, kk = (c & 7) * 8;
            cp16(sAh[s] + row * STR + kk, Ahi + (size_t)(m0 + row) * lda + k0 + kk);
        }
#pragma unroll
        for (int r = 0; r < NSEG * 2; r++) {
            int c = tid + r * 256;
            int srow = c >> 3, kk = (c & 7) * 8;
            if (MODE == 1) {
                int seg = srow >> 6;
                // seg 2 live only in feat half (kt<4), seg 3 only in ma half (kt>=4)
                if ((seg == 2 && kt >= 4) || (seg == 3 && kt < 4)) continue;
            }
            int srcrow = (MODE == 2) ? (n0 + srow) : ((srow >> 6) * 256 + n0 + (srow & 63));
            cp16(sB[s] + srow * STR + kk, B + (size_t)srcrow * K + k0 + kk);
        }
    };

    wmma::fragment<wmma::accumulator, 16, 16, 16, float> acc[NSEG][MI][2];
#pragma unroll
    for (int g = 0; g < NSEG; g++)
#pragma unroll
        for (int i = 0; i < MI; i++)
#pragma unroll
            for (int j = 0; j < 2; j++) wmma::fill_fragment(acc[g][i][j], 0.0f);

    load_tile(0, 0); cp_commit();
    if (KT > 1) { load_tile(1, 1); cp_commit(); }

    for (int kt = 0; kt < KT; kt++) {
        if (kt == KT - 1) cp_wait<0>(); else cp_wait<1>();
        __syncthreads();
        const int s = kt & 1;
        const bool featHalf = (MODE != 1) || (kt < 4);
#pragma unroll
        for (int kc = 0; kc < 64; kc += 16) {
            wmma::fragment<wmma::matrix_a, 16, 16, 16, __half, wmma::row_major> ah[MI];
#pragma unroll
            for (int i = 0; i < MI; i++)
                wmma::load_matrix_sync(ah[i], sAh[s] + (wm * 16 * MI + i * 16) * STR + kc, STR);
#pragma unroll
            for (int g = 0; g < NSEG; g++) {
                if (MODE == 1) {
                    if ((g == 2 && !featHalf) || (g == 3 && featHalf)) continue;
                }
                wmma::fragment<wmma::matrix_b, 16, 16, 16, __half, wmma::col_major> b[2];
#pragma unroll
                for (int j = 0; j < 2; j++)
                    wmma::load_matrix_sync(b[j], sB[s] + (g * 64 + wn * 32 + j * 16) * STR + kc, STR);
#pragma unroll
                for (int i = 0; i < MI; i++)
#pragma unroll
                    for (int j = 0; j < 2; j++)
                        wmma::mma_sync(acc[g][i][j], ah[i], b[j], acc[g][i][j]);
            }
        }
        __syncthreads();
        if (kt + 2 < KT) { load_tile(kt & 1, kt + 2); cp_commit(); }
    }

    // ---------------- epilogue ----------------
    float* wbuf = (float*)smem_raw;
    float* sX = wbuf + 8 * NSEG * 320;
    constexpr int XW = (MODE == 1) ? 4 : 8;
    float* sW = sX + BM * XW;

    if (MODE != 2) {
#pragma unroll
        for (int r = 0; r < (BM * XW + 255) / 256; r++) {
            int c = tid + r * 256;
            if (c < BM * XW) sX[c] = xw[(size_t)(m0 + (c / XW)) * XW + (c % XW)];
        }
#pragma unroll
        for (int r = 0; r < 6; r++) {
            int c = tid + r * 256;
            int srow = c >> 3, k = c & 7;
            sW[c] = swg[(size_t)((srow >> 6) * 256 + n0 + (srow & 63)) * 8 + k];
        }
    }
    __syncthreads();

    float* wb = wbuf + wid * NSEG * 320;
    const int r_ = lane >> 1;
    const int c0_ = (lane & 1) * 8;

#pragma unroll
    for (int i = 0; i < MI; i++) {
#pragma unroll
        for (int j = 0; j < 2; j++) {
#pragma unroll
            for (int g = 0; g < NSEG; g++)
                wmma::store_matrix_sync(wb + g * 320, acc[g][i][j], 20, wmma::mem_row_major);
            __syncwarp();

            const int mloc = wm * 16 * MI + i * 16 + r_;
            const int m = m0 + mloc;
            const int nl0 = wn * 32 + j * 16 + c0_;
            const int nabs = n0 + nl0;

            __half oh8[8], ol8[8];

            if (MODE == 2) {
                float4 b0 = *(const float4*)&xw[nabs];
                float4 b1 = *(const float4*)&xw[nabs + 4];
                float bia[8] = {b0.x,b0.y,b0.z,b0.w,b1.x,b1.y,b1.z,b1.w};
                float ov[8];
#pragma unroll
                for (int cc = 0; cc < 8; cc++) {
                    float v = eluf_(wb[r_ * 20 + c0_ + cc] + bia[cc]);
                    ov[cc] = v;
                    oh8[cc] = __float2half_rn(v);
                }
                if (Ofp) {
                    *(float4*)&Ofp[(size_t)m * 256 + nabs] = make_float4(ov[0],ov[1],ov[2],ov[3]);
                    *(float4*)&Ofp[(size_t)m * 256 + nabs + 4] = make_float4(ov[4],ov[5],ov[6],ov[7]);
                }
                if (Ohi) {
                    *(uint4*)&Ohi[(size_t)m * ldo + nabs] = *(uint4*)oh8;
                }
            } else {
                uint4 hv4 = *(const uint4*)&oldHi[(size_t)m * oldLd + nabs];
                uint4 lv4 = *(const uint4*)&oldLo[(size_t)m * oldLd + nabs];
                const __half* hvp = (const __half*)&hv4;
                const __half* lvp = (const __half*)&lv4;
                float xr[XW];
#pragma unroll
                for (int k = 0; k < XW; k++) xr[k] = sX[mloc * XW + k];
#pragma unroll
                for (int cc = 0; cc < 8; cc++) {
                    int nl = nl0 + cc;
                    const float* w0 = sW + (0 * 64 + nl) * 8;
                    const float* w1 = sW + (1 * 64 + nl) * 8;
                    const float* w2 = sW + (2 * 64 + nl) * 8;
                    float a0 = wb[0 * 320 + r_ * 20 + c0_ + cc];
                    float a1 = wb[1 * 320 + r_ * 20 + c0_ + cc];
                    float a2 = wb[2 * 320 + r_ * 20 + c0_ + cc];
                    float gi_r, gi_z, gi_n, rr, zz, nn;
                    if (MODE == 0) {
                        gi_r = w0[5]; gi_z = w1[5]; gi_n = w2[5];
#pragma unroll
                        for (int k = 0; k < 5; k++) {
                            gi_r += xr[k] * w0[k];
                            gi_z += xr[k] * w1[k];
                            gi_n += xr[k] * w2[k];
                        }
                        rr = fsig(gi_r + a0 + w0[6]);
                        zz = fsig(gi_z + a1 + w1[6]);
                        nn = ftanh_(gi_n + rr * (a2 + w2[6]));
                    } else {
                        float a3 = wb[3 * 320 + r_ * 20 + c0_ + cc];
                        gi_r = w0[3]; gi_z = w1[3]; gi_n = w2[3];
#pragma unroll
                        for (int k = 0; k < 3; k++) {
                            gi_r += xr[k] * w0[k];
                            gi_z += xr[k] * w1[k];
                            gi_n += xr[k] * w2[k];
                        }
                        rr = fsig(gi_r + a0 + w0[4]);
                        zz = fsig(gi_z + a1 + w1[4]);
                        nn = ftanh_(gi_n + a2 + rr * (a3 + w2[4]));
                    }
                    float hold = __half2float(hvp[cc]) + __half2float(lvp[cc]);
                    float hnew = (1.0f - zz) * nn + zz * hold;
                    split_fp16(hnew, oh8[cc], ol8[cc]);
                }
                *(uint4*)&Ohi[(size_t)m * ldo + nabs] = *(uint4*)oh8;
                *(uint4*)&Olo[(size_t)m * ldo + nabs] = *(uint4*)ol8;
            }
            __syncwarp();
        }
    }
}

// ---------------- entity max-pool (hi planes only) ----------------
__global__ void pool_kernel(const __half* __restrict__ phi,
                            __half* __restrict__ xcat_hi)
{
    int idx = blockIdx.x * blockDim.x + threadIdx.x;
    if (idx >= MA_ROWS * 32) return;
    int m = idx >> 5, c8 = (idx & 31) * 8;
    float v[8];
#pragma unroll
    for (int k = 0; k < 8; k++) v[k] = -1e30f;
#pragma unroll
    for (int e = 0; e < EE; e++) {
        size_t off = (size_t)(m * EE + e) * HH + c8;
        uint4 h4 = *(const uint4*)&phi[off];
        const __half* hp = (const __half*)&h4;
#pragma unroll
        for (int k = 0; k < 8; k++)
            v[k] = fmaxf(v[k], __half2float(hp[k]));
    }
    __half h8[8];
#pragma unroll
    for (int k = 0; k < 8; k++) h8[k] = __float2half_rn(v[k]);
    *(uint4*)&xcat_hi[(size_t)m * 512 + c8] = *(uint4*)h8;
}

// ---------------- head ----------------
__global__ void head_kernel(const float* __restrict__ t2,
                            const float* __restrict__ Wm2, const float* __restrict__ bm2,
                            float* __restrict__ out, int tstep)
{
    int warp = (blockIdx.x * blockDim.x + threadIdx.x) >> 5;
    int lane = threadIdx.x & 31;
    if (warp >= MA_ROWS) return;
    float s0 = 0.0f, s1 = 0.0f;
    for (int k = lane; k < HH; k += 32) {
        float x = t2[warp * HH + k];
        s0 += x * Wm2[k];
        s1 += x * Wm2[HH + k];
    }
#pragma unroll
    for (int off = 16; off; off >>= 1) {
        s0 += __shfl_xor_sync(0xffffffffu, s0, off);
        s1 += __shfl_xor_sync(0xffffffffu, s1, off);
    }
    if (lane == 0) {
        out[((size_t)tstep * MA_ROWS + warp) * 2 + 0] = ftanh_(s0 + bm2[0]) * 0.05f;
        out[((size_t)tstep * MA_ROWS + warp) * 2 + 1] = ftanh_(s1 + bm2[1]) * 0.05f;
    }
}

// ---------------- host launcher ----------------
extern "C" void kernel_launch(void* const* d_in, const int* in_sizes, int n_in,
                              void* d_out, int out_size)
{
    const float* obs    = (const float*)d_in[0];
    const float* phys   = (const float*)d_in[1];
    const float* goals  = (const float*)d_in[2];
    const float* mem_p  = (const float*)d_in[3];
    const float* mem_a  = (const float*)d_in[4];
    const float* Wih_p  = (const float*)d_in[5];
    const float* Whh_p  = (const float*)d_in[6];
    const float* bih_p  = (const float*)d_in[7];
    const float* bhh_p  = (const float*)d_in[8];
    const float* Wfc_p  = (const float*)d_in[9];
    const float* bfc_p  = (const float*)d_in[10];
    const float* Wih_a  = (const float*)d_in[11];
    const float* Whh_a  = (const float*)d_in[12];
    const float* bih_a  = (const float*)d_in[13];
    const float* bhh_a  = (const float*)d_in[14];
    const float* Wfc_a  = (const float*)d_in[15];
    const float* bfc_a  = (const float*)d_in[16];
    const float* Wm1    = (const float*)d_in[17];
    const float* bm1    = (const float*)d_in[18];
    const float* Wm2    = (const float*)d_in[19];
    const float* bm2    = (const float*)d_in[20];
    float* out = (float*)d_out;

    void* p;
    __half *h_hi[3], *h_lo[3], *xc_hi[2], *xc_lo[2];
    cudaGetSymbolAddress(&p, g_h_hi);
    h_hi[0] = (__half*)p; h_hi[1] = h_hi[0] + (size_t)MP_ROWS*HH; h_hi[2] = h_hi[1] + (size_t)MP_ROWS*HH;
    cudaGetSymbolAddress(&p, g_h_lo);
    h_lo[0] = (__half*)p; h_lo[1] = h_lo[0] + (size_t)MP_ROWS*HH; h_lo[2] = h_lo[1] + (size_t)MP_ROWS*HH;
    cudaGetSymbolAddress(&p, g_xcat_hi); xc_hi[0] = (__half*)p; xc_hi[1] = xc_hi[0] + (size_t)MA_ROWS*512;
    cudaGetSymbolAddress(&p, g_xcat_lo); xc_lo[0] = (__half*)p; xc_lo[1] = xc_lo[0] + (size_t)MA_ROWS*512;
    cudaGetSymbolAddress(&p, g_proc_hi); __half* proc_hi = (__half*)p;
    cudaGetSymbolAddress(&p, g_t1_hi);   __half* t1_hi = (__half*)p;
    cudaGetSymbolAddress(&p, g_t2);      float* t2 = (float*)p;
    cudaGetSymbolAddress(&p, g_xp8);     float* xp8 = (float*)p;
    cudaGetSymbolAddress(&p, g_xa4);     float* xa4 = (float*)p;
    cudaGetSymbolAddress(&p, g_Wp8);     float* Wp8 = (float*)p;
    cudaGetSymbolAddress(&p, g_Wa8);     float* Wa8 = (float*)p;
    cudaGetSymbolAddress(&p, g_Whhp);    __half* Whhp = (__half*)p;
    cudaGetSymbolAddress(&p, g_Wfcp);    __half* Wfcp = (__half*)p;
    cudaGetSymbolAddress(&p, g_Wcat);    __half* Wcat = (__half*)p;
    cudaGetSymbolAddress(&p, g_Wfca);    __half* Wfca = (__half*)p;
    cudaGetSymbolAddress(&p, g_Wm1);     __half* Wm1h = (__half*)p;

    const int SM_0_128 = (2*128*72 + 2*3*64*72) * 2;   // 92160
    const int SM_1_64  = (2*64*72  + 2*4*64*72) * 2;   // 92160
    const int SM_2_128 = (2*128*72 + 2*1*64*72) * 2;   // 55296
    const int SM_2_64  = (2*64*72  + 2*1*64*72) * 2;   // 36864
    cudaFuncSetAttribute((const void*)fused_kernel<0,128>, cudaFuncAttributeMaxDynamicSharedMemorySize, SM_0_128);
    cudaFuncSetAttribute((const void*)fused_kernel<1,64>,  cudaFuncAttributeMaxDynamicSharedMemorySize, SM_1_64);
    cudaFuncSetAttribute((const void*)fused_kernel<2,128>, cudaFuncAttributeMaxDynamicSharedMemorySize, SM_2_128);
    cudaFuncSetAttribute((const void*)fused_kernel<2,64>,  cudaFuncAttributeMaxDynamicSharedMemorySize, SM_2_64);

    // ---- one-time stream/event setup ----
    static cudaStream_t sA = nullptr, sB = nullptr;
    static cudaEvent_t evFork = nullptr, evJoinA = nullptr, evJoinB = nullptr;
    static cudaEvent_t evG[TT], evF[TT], evP[TT], evA[TT];
    if (sA == nullptr) {
        cudaStreamCreateWithFlags(&sA, cudaStreamNonBlocking);
        cudaStreamCreateWithFlags(&sB, cudaStreamNonBlocking);
        cudaEventCreateWithFlags(&evFork, cudaEventDisableTiming);
        cudaEventCreateWithFlags(&evJoinA, cudaEventDisableTiming);
        cudaEventCreateWithFlags(&evJoinB, cudaEventDisableTiming);
        for (int i = 0; i < TT; i++) {
            cudaEventCreateWithFlags(&evG[i], cudaEventDisableTiming);
            cudaEventCreateWithFlags(&evF[i], cudaEventDisableTiming);
            cudaEventCreateWithFlags(&evP[i], cudaEventDisableTiming);
            cudaEventCreateWithFlags(&evA[i], cudaEventDisableTiming);
        }
    }

    cudaStream_t s0 = 0;

    // ---- fork sB immediately so its prep work is rooted in the capture ----
    cudaEventRecord(evFork, s0);
    cudaStreamWaitEvent(sB, evFork, 0);

    // ---- gru_p-critical prep on s0 ----
    split_kernel<<<(MP_ROWS*HH + 255)/256, 256, 0, s0>>>(mem_p, h_hi[0], h_lo[0], MP_ROWS*HH);
    conv_kernel<<<(G3H*HH + 255)/256, 256, 0, s0>>>(Whh_p, Whhp, G3H*HH);
    prep_xp_kernel<<<(MP_ROWS + 255)/256, 256, 0, s0>>>(obs, phys, xp8);
    prep_wp8_kernel<<<(G3H + 255)/256, 256, 0, s0>>>(Wih_p, bih_p, bhh_p, Wp8);

    // ---- everything else on sB (hides under gru_p(0)) ----
    split_strided_kernel<<<(MA_ROWS*HH + 255)/256, 256, 0, sB>>>(mem_a, xc_hi[0] + 256, xc_lo[0] + 256, MA_ROWS, HH, 512);
    conv_kernel<<<(HH*HH + 255)/256, 256, 0, sB>>>(Wfc_p, Wfcp, HH*HH);
    conv_kernel<<<(HH*HH + 255)/256, 256, 0, sB>>>(Wfc_a, Wfca, HH*HH);
    conv_kernel<<<(HH*HH + 255)/256, 256, 0, sB>>>(Wm1, Wm1h, HH*HH);
    build_wcat_kernel<<<(1024*512 + 255)/256, 256, 0, sB>>>(Wih_a, Whh_a, Wcat);
    prep_xa_kernel<<<(MA_ROWS + 255)/256, 256, 0, sB>>>(goals, xa4);
    prep_wa8_kernel<<<(G3H + 255)/256, 256, 0, sB>>>(Wih_a, bih_a, bhh_a, Wa8);

    // ---- recurrence ----
    // s0 : gru_p chain (critical path). sB : fc_p + pool. sA : action chain.
    // h is triple-buffered: gru_p(t) reads h[t%3], writes h[(t+1)%3] (read by fc_p(t)).
    // WAR: gru_p(t) overwrites the buffer fc_p(t-3) read -> wait evF[t-3].
    // xcat stays 2-way with the evA[t-2] guard on pool.
    for (int t = 0; t < TT; t++) {
        int cur = t % 3;
        int nxt = (t + 1) % 3;
        int xc = t & 1, xn = (t + 1) & 1;
        // ---- physical GRU on s0 ----
        if (t >= 3) cudaStreamWaitEvent(s0, evF[t - 3], 0);
        fused_kernel<0,128><<<dim3(MP_ROWS/128, 4), 256, SM_0_128, s0>>>(
            h_hi[cur], HH, Whhp, xp8, Wp8,
            h_hi[cur], h_lo[cur], HH,
            h_hi[nxt], h_lo[nxt], HH, nullptr);
        cudaEventRecord(evG[t], s0);

        // ---- fc_p + pool on sB ----
        cudaStreamWaitEvent(sB, evG[t], 0);
        fused_kernel<2,128><<<dim3(MP_ROWS/128, 4), 256, SM_2_128, sB>>>(
            h_hi[nxt], HH, Wfcp, bfc_p, nullptr,
            nullptr, nullptr, 0,
            proc_hi, nullptr, HH, nullptr);
        cudaEventRecord(evF[t], sB);
        if (t >= 2) cudaStreamWaitEvent(sB, evA[t - 2], 0);
        pool_kernel<<<(MA_ROWS*32 + 255)/256, 256, 0, sB>>>(proc_hi, xc_hi[xc]);
        cudaEventRecord(evP[t], sB);

        // ---- action chain on sA ----
        cudaStreamWaitEvent(sA, evP[t], 0);
        fused_kernel<1,64><<<dim3(MA_ROWS/64, 4), 256, SM_1_64, sA>>>(
            xc_hi[xc], 512, Wcat, xa4, Wa8,
            xc_hi[xc] + 256, xc_lo[xc] + 256, 512,
            xc_hi[xn] + 256, xc_lo[xn] + 256, 512, nullptr);
        cudaEventRecord(evA[t], sA);
        fused_kernel<2,64><<<dim3(MA_ROWS/64, 4), 256, SM_2_64, sA>>>(
            xc_hi[xn] + 256, 512, Wfca, bfc_a, nullptr,
            nullptr, nullptr, 0,
            t1_hi, nullptr, HH, nullptr);
        fused_kernel<2,64><<<dim3(MA_ROWS/64, 4), 256, SM_2_64, sA>>>(
            t1_hi, HH, Wm1h, bm1, nullptr,
            nullptr, nullptr, 0,
            nullptr, nullptr, 0, t2);
        head_kernel<<<(MA_ROWS*32 + 255)/256, 256, 0, sA>>>(t2, Wm2, bm2, out, t);
    }

    // join side streams back into stream 0
    cudaEventRecord(evJoinA, sA);
    cudaStreamWaitEvent(s0, evJoinA, 0);
    cudaEventRecord(evJoinB, sB);
    cudaStreamWaitEvent(s0, evJoinB, 0);
}

// round 15
// speedup vs baseline: 1.1484x; 1.0285x over previous
#include <cuda_runtime.h>
#include <cuda_fp16.h>
#include <mma.h>
#include <math.h>
#include <stdint.h>

using namespace nvcuda;

#define BB 512
#define AA 4
#define EE 10
#define HH 256
#define TT 10
#define MP_ROWS (BB*AA*EE)   // 20480
#define MA_ROWS (BB*AA)      // 2048
#define G3H (3*HH)           // 768

// ---------------- scratch ----------------
__device__ __half g_h_hi[3][MP_ROWS * HH];
__device__ __half g_h_lo[3][MP_ROWS * HH];
__device__ __half g_xcat_hi[2][MA_ROWS * 512];   // [feat | ma]
__device__ __half g_xcat_lo[2][MA_ROWS * 512];
__device__ __half g_proc_hi[MP_ROWS * HH];
__device__ __half g_t1_hi[MA_ROWS * HH];
__device__ float g_t2[MA_ROWS * HH];
__device__ float g_xp8[MP_ROWS * 8];     // [ob0,ob1,ph0,ph1,ph2,0,0,0]
__device__ float g_xa4[MA_ROWS * 4];     // [g0,g1,g2,0]
__device__ float g_Wp8[G3H * 8];         // [w0..w4, bih, bhh, 0]
__device__ float g_Wa8[G3H * 8];         // [wg0..2, bih, bhh, 0,0,0]
__device__ __half g_Whhp[G3H * HH];
__device__ __half g_Wfcp[HH * HH];
__device__ __half g_Wcat[1024 * 512];
__device__ __half g_Wfca[HH * HH];
__device__ __half g_Wm1[HH * HH];

// ---------------- helpers ----------------
__device__ __forceinline__ float fsig(float x) {
    float e = __expf(-x);
    return __fdividef(1.0f, 1.0f + e);
}
__device__ __forceinline__ float ftanh_(float x) {
    float xc = fmaxf(fminf(x, 15.0f), -15.0f);
    float e = __expf(-2.0f * xc);
    return __fdividef(1.0f - e, 1.0f + e);
}
__device__ __forceinline__ float eluf_(float x) { return x > 0.0f ? x : expm1f(x); }
__device__ __forceinline__ void split_fp16(float x, __half& hi, __half& lo) {
    hi = __float2half_rn(x);
    lo = __float2half_rn(x - __half2float(hi));
}
__device__ __forceinline__ void cp16(void* dst, const void* src) {
    unsigned d = (unsigned)__cvta_generic_to_shared(dst);
    asm volatile("cp.async.cg.shared.global [%0], [%1], 16;\n" :: "r"(d), "l"(src));
}
__device__ __forceinline__ void cp_commit() { asm volatile("cp.async.commit_group;\n" ::); }
template<int N> __device__ __forceinline__ void cp_wait() { asm volatile("cp.async.wait_group %0;\n" :: "n"(N)); }

// ---------------- prep kernels ----------------
__global__ void prep_xp_kernel(const float* __restrict__ obs, const float* __restrict__ phys,
                               float* __restrict__ xp8)
{
    int r = blockIdx.x * blockDim.x + threadIdx.x;
    if (r >= MP_ROWS) return;
    int b = r / (AA*EE);
    int e = r % EE;
    float* o = xp8 + r * 8;
    o[0] = obs[r*2+0]; o[1] = obs[r*2+1];
    const float* ph = phys + (b * EE + e) * 3;
    o[2] = ph[0]; o[3] = ph[1]; o[4] = ph[2];
    o[5] = 0.f; o[6] = 0.f; o[7] = 0.f;
}
__global__ void prep_wp8_kernel(const float* __restrict__ Wih, const float* __restrict__ bih,
                                const float* __restrict__ bhh, float* __restrict__ Wp8)
{
    int r = blockIdx.x * blockDim.x + threadIdx.x;
    if (r >= G3H) return;
    float* o = Wp8 + r * 8;
#pragma unroll
    for (int k = 0; k < 5; k++) o[k] = Wih[r*5+k];
    o[5] = bih[r]; o[6] = bhh[r]; o[7] = 0.f;
}
__global__ void prep_xa_kernel(const float* __restrict__ goals, float* __restrict__ xa4)
{
    int m = blockIdx.x * blockDim.x + threadIdx.x;
    if (m >= MA_ROWS) return;
    float* o = xa4 + m * 4;
    o[0] = goals[m*3+0]; o[1] = goals[m*3+1]; o[2] = goals[m*3+2]; o[3] = 0.f;
}
__global__ void prep_wa8_kernel(const float* __restrict__ Wih, const float* __restrict__ bih,
                                const float* __restrict__ bhh, float* __restrict__ Wa8)
{
    int r = blockIdx.x * blockDim.x + threadIdx.x;
    if (r >= G3H) return;
    float* o = Wa8 + r * 8;
    o[0] = Wih[r*259+256]; o[1] = Wih[r*259+257]; o[2] = Wih[r*259+258];
    o[3] = bih[r]; o[4] = bhh[r]; o[5] = 0.f; o[6] = 0.f; o[7] = 0.f;
}
__global__ void split_kernel(const float* __restrict__ src,
                             __half* __restrict__ hi, __half* __restrict__ lo, int n)
{
    int i = blockIdx.x * blockDim.x + threadIdx.x;
    if (i >= n) return;
    split_fp16(src[i], hi[i], lo[i]);
}
__global__ void split_strided_kernel(const float* __restrict__ src,
                                     __half* __restrict__ hi, __half* __restrict__ lo,
                                     int rows, int cols, int ldo)
{
    int i = blockIdx.x * blockDim.x + threadIdx.x;
    if (i >= rows * cols) return;
    int r = i / cols, c = i - r * cols;
    split_fp16(src[i], hi[r * ldo + c], lo[r * ldo + c]);
}
__global__ void conv_kernel(const float* __restrict__ src, __half* __restrict__ dst, int n)
{
    int i = blockIdx.x * blockDim.x + threadIdx.x;
    if (i >= n) return;
    dst[i] = __float2half_rn(src[i]);
}
// Wcat [1024, 512]: rows g*256+n. g=0:[Wih_r|Whh_r] g=1:[Wih_z|Whh_z] g=2:[Wih_n|0] g=3:[0|Whh_n]
__global__ void build_wcat_kernel(const float* __restrict__ Wih,  // [768,259]
                                  const float* __restrict__ Whh,  // [768,256]
                                  __half* __restrict__ Wcat)
{
    int idx = blockIdx.x * blockDim.x + threadIdx.x;
    if (idx >= 1024 * 512) return;
    int row = idx >> 9, col = idx & 511;
    int g = row >> 8, n = row & 255;
    float v = 0.0f;
    if (g < 2) {
        v = (col < 256) ? Wih[(g * 256 + n) * 259 + col] : Whh[(g * 256 + n) * 256 + (col - 256)];
    } else if (g == 2) {
        if (col < 256) v = Wih[(512 + n) * 259 + col];
    } else {
        if (col >= 256) v = Whh[(512 + n) * 256 + (col - 256)];
    }
    Wcat[idx] = __float2half_rn(v);
}

// ---------------- fused fp16 single-pass GEMM kernel (BK=64) ----------------
// MODE 0: physical GRU  (NSEG=3, K=256), MODE 1: action GRU (NSEG=4, K=512),
// MODE 2: ELU layer     (NSEG=1, K=256).
// Warp grid: MODE 0/1 use 2(m)x4(n) (warp tile (BM/2)x16, better MMA:ldsm ratio);
// MODE 2 keeps 4(m)x2(n). Per-output k-order identical -> bit-identical numerics.
template<int MODE, int BM>
__global__ __launch_bounds__(256) void fused_kernel(
    const __half* __restrict__ Ahi, int lda,
    const __half* __restrict__ B,
    const float* __restrict__ xw,     // xp8 / xa4 / bias
    const float* __restrict__ swg,    // Wp8 / Wa8 / unused
    const __half* __restrict__ oldHi, const __half* __restrict__ oldLo, int oldLd,
    __half* __restrict__ Ohi, __half* __restrict__ Olo, int ldo,
    float* __restrict__ Ofp)
{
    constexpr int NSEG = (MODE == 0) ? 3 : ((MODE == 1) ? 4 : 1);
    constexpr int K = (MODE == 1) ? 512 : 256;
    constexpr int KT = K / 64;
    constexpr int WN = (MODE == 2) ? 2 : 4;       // warps along n
    constexpr int WM = 8 / WN;                    // warps along m
    constexpr int MI = BM / WM / 16;              // a-frags per warp
    constexpr int NJ = 64 / WN / 16;              // b-frags per warp per seg
    constexpr int STR = 72;
    constexpr int AITER = BM / 32;
    constexpr int AHS = BM * STR;
    constexpr int BHS = NSEG * 64 * STR;

    extern __shared__ __align__(16) char smem_raw[];
    __half* sm = (__half*)smem_raw;
    __half* sAh[2] = { sm,           sm + AHS };
    __half* sB[2]  = { sm + 2*AHS,   sm + 2*AHS + BHS };

    const int m0 = blockIdx.x * BM;
    const int n0 = blockIdx.y * 64;
    const int tid = threadIdx.x;
    const int wid = tid >> 5;
    const int lane = tid & 31;
    const int wm = wid / WN, wn = wid % WN;

    auto load_tile = [&](int s, int kt) {
        const int k0 = kt * 64;
#pragma unroll
        for (int r = 0; r < AITER; r++) {
            int c = tid + r * 256;
            int row = c >> 3, kk = (c & 7) * 8;
            cp16(sAh[s] + row * STR + kk, Ahi + (size_t)(m0 + row) * lda + k0 + kk);
        }
#pragma unroll
        for (int r = 0; r < NSEG * 2; r++) {
            int c = tid + r * 256;
            int srow = c >> 3, kk = (c & 7) * 8;
            if (MODE == 1) {
                int seg = srow >> 6;
                if ((seg == 2 && kt >= 4) || (seg == 3 && kt < 4)) continue;
            }
            int srcrow = (MODE == 2) ? (n0 + srow) : ((srow >> 6) * 256 + n0 + (srow & 63));
            cp16(sB[s] + srow * STR + kk, B + (size_t)srcrow * K + k0 + kk);
        }
    };

    wmma::fragment<wmma::accumulator, 16, 16, 16, float> acc[NSEG][MI][NJ];
#pragma unroll
    for (int g = 0; g < NSEG; g++)
#pragma unroll
        for (int i = 0; i < MI; i++)
#pragma unroll
            for (int j = 0; j < NJ; j++) wmma::fill_fragment(acc[g][i][j], 0.0f);

    load_tile(0, 0); cp_commit();
    if (KT > 1) { load_tile(1, 1); cp_commit(); }

    for (int kt = 0; kt < KT; kt++) {
        if (kt == KT - 1) cp_wait<0>(); else cp_wait<1>();
        __syncthreads();
        const int s = kt & 1;
        const bool featHalf = (MODE != 1) || (kt < 4);
#pragma unroll
        for (int kc = 0; kc < 64; kc += 16) {
            wmma::fragment<wmma::matrix_a, 16, 16, 16, __half, wmma::row_major> ah[MI];
#pragma unroll
            for (int i = 0; i < MI; i++)
                wmma::load_matrix_sync(ah[i], sAh[s] + (wm * 16 * MI + i * 16) * STR + kc, STR);
#pragma unroll
            for (int g = 0; g < NSEG; g++) {
                if (MODE == 1) {
                    if ((g == 2 && !featHalf) || (g == 3 && featHalf)) continue;
                }
                wmma::fragment<wmma::matrix_b, 16, 16, 16, __half, wmma::col_major> b[NJ];
#pragma unroll
                for (int j = 0; j < NJ; j++)
                    wmma::load_matrix_sync(b[j], sB[s] + (g * 64 + (wn * NJ + j) * 16) * STR + kc, STR);
#pragma unroll
                for (int i = 0; i < MI; i++)
#pragma unroll
                    for (int j = 0; j < NJ; j++)
                        wmma::mma_sync(acc[g][i][j], ah[i], b[j], acc[g][i][j]);
            }
        }
        __syncthreads();
        if (kt + 2 < KT) { load_tile(kt & 1, kt + 2); cp_commit(); }
    }

    // ---------------- epilogue ----------------
    float* wbuf = (float*)smem_raw;
    float* sX = wbuf + 8 * NSEG * 320;
    constexpr int XW = (MODE == 1) ? 4 : 8;
    float* sW = sX + BM * XW;

    if (MODE != 2) {
#pragma unroll
        for (int r = 0; r < (BM * XW + 255) / 256; r++) {
            int c = tid + r * 256;
            if (c < BM * XW) sX[c] = xw[(size_t)(m0 + (c / XW)) * XW + (c % XW)];
        }
#pragma unroll
        for (int r = 0; r < 6; r++) {
            int c = tid + r * 256;
            int srow = c >> 3, k = c & 7;
            sW[c] = swg[(size_t)((srow >> 6) * 256 + n0 + (srow & 63)) * 8 + k];
        }
    }
    __syncthreads();

    float* wb = wbuf + wid * NSEG * 320;
    const int r_ = lane >> 1;
    const int c0_ = (lane & 1) * 8;

#pragma unroll
    for (int i = 0; i < MI; i++) {
#pragma unroll
        for (int j = 0; j < NJ; j++) {
#pragma unroll
            for (int g = 0; g < NSEG; g++)
                wmma::store_matrix_sync(wb + g * 320, acc[g][i][j], 20, wmma::mem_row_major);
            __syncwarp();

            const int mloc = wm * 16 * MI + i * 16 + r_;
            const int m = m0 + mloc;
            const int nl0 = (wn * NJ + j) * 16 + c0_;
            const int nabs = n0 + nl0;

            __half oh8[8], ol8[8];

            if (MODE == 2) {
                float4 b0 = *(const float4*)&xw[nabs];
                float4 b1 = *(const float4*)&xw[nabs + 4];
                float bia[8] = {b0.x,b0.y,b0.z,b0.w,b1.x,b1.y,b1.z,b1.w};
                float ov[8];
#pragma unroll
                for (int cc = 0; cc < 8; cc++) {
                    float v = eluf_(wb[r_ * 20 + c0_ + cc] + bia[cc]);
                    ov[cc] = v;
                    oh8[cc] = __float2half_rn(v);
                }
                if (Ofp) {
                    *(float4*)&Ofp[(size_t)m * 256 + nabs] = make_float4(ov[0],ov[1],ov[2],ov[3]);
                    *(float4*)&Ofp[(size_t)m * 256 + nabs + 4] = make_float4(ov[4],ov[5],ov[6],ov[7]);
                }
                if (Ohi) {
                    *(uint4*)&Ohi[(size_t)m * ldo + nabs] = *(uint4*)oh8;
                }
            } else {
                uint4 hv4 = *(const uint4*)&oldHi[(size_t)m * oldLd + nabs];
                uint4 lv4 = *(const uint4*)&oldLo[(size_t)m * oldLd + nabs];
                const __half* hvp = (const __half*)&hv4;
                const __half* lvp = (const __half*)&lv4;
                float xr[XW];
#pragma unroll
                for (int k = 0; k < XW; k++) xr[k] = sX[mloc * XW + k];
#pragma unroll
                for (int cc = 0; cc < 8; cc++) {
                    int nl = nl0 + cc;
                    const float* w0 = sW + (0 * 64 + nl) * 8;
                    const float* w1 = sW + (1 * 64 + nl) * 8;
                    const float* w2 = sW + (2 * 64 + nl) * 8;
                    float a0 = wb[0 * 320 + r_ * 20 + c0_ + cc];
                    float a1 = wb[1 * 320 + r_ * 20 + c0_ + cc];
                    float a2 = wb[2 * 320 + r_ * 20 + c0_ + cc];
                    float gi_r, gi_z, gi_n, rr, zz, nn;
                    if (MODE == 0) {
                        gi_r = w0[5]; gi_z = w1[5]; gi_n = w2[5];
#pragma unroll
                        for (int k = 0; k < 5; k++) {
                            gi_r += xr[k] * w0[k];
                            gi_z += xr[k] * w1[k];
                            gi_n += xr[k] * w2[k];
                        }
                        rr = fsig(gi_r + a0 + w0[6]);
                        zz = fsig(gi_z + a1 + w1[6]);
                        nn = ftanh_(gi_n + rr * (a2 + w2[6]));
                    } else {
                        float a3 = wb[3 * 320 + r_ * 20 + c0_ + cc];
                        gi_r = w0[3]; gi_z = w1[3]; gi_n = w2[3];
#pragma unroll
                        for (int k = 0; k < 3; k++) {
                            gi_r += xr[k] * w0[k];
                            gi_z += xr[k] * w1[k];
                            gi_n += xr[k] * w2[k];
                        }
                        rr = fsig(gi_r + a0 + w0[4]);
                        zz = fsig(gi_z + a1 + w1[4]);
                        nn = ftanh_(gi_n + a2 + rr * (a3 + w2[4]));
                    }
                    float hold = __half2float(hvp[cc]) + __half2float(lvp[cc]);
                    float hnew = (1.0f - zz) * nn + zz * hold;
                    split_fp16(hnew, oh8[cc], ol8[cc]);
                }
                *(uint4*)&Ohi[(size_t)m * ldo + nabs] = *(uint4*)oh8;
                *(uint4*)&Olo[(size_t)m * ldo + nabs] = *(uint4*)ol8;
            }
            __syncwarp();
        }
    }
}

// ---------------- entity max-pool (hi planes only) ----------------
__global__ void pool_kernel(const __half* __restrict__ phi,
                            __half* __restrict__ xcat_hi)
{
    int idx = blockIdx.x * blockDim.x + threadIdx.x;
    if (idx >= MA_ROWS * 32) return;
    int m = idx >> 5, c8 = (idx & 31) * 8;
    float v[8];
#pragma unroll
    for (int k = 0; k < 8; k++) v[k] = -1e30f;
#pragma unroll
    for (int e = 0; e < EE; e++) {
        size_t off = (size_t)(m * EE + e) * HH + c8;
        uint4 h4 = *(const uint4*)&phi[off];
        const __half* hp = (const __half*)&h4;
#pragma unroll
        for (int k = 0; k < 8; k++)
            v[k] = fmaxf(v[k], __half2float(hp[k]));
    }
    __half h8[8];
#pragma unroll
    for (int k = 0; k < 8; k++) h8[k] = __float2half_rn(v[k]);
    *(uint4*)&xcat_hi[(size_t)m * 512 + c8] = *(uint4*)h8;
}

// ---------------- head ----------------
__global__ void head_kernel(const float* __restrict__ t2,
                            const float* __restrict__ Wm2, const float* __restrict__ bm2,
                            float* __restrict__ out, int tstep)
{
    int warp = (blockIdx.x * blockDim.x + threadIdx.x) >> 5;
    int lane = threadIdx.x & 31;
    if (warp >= MA_ROWS) return;
    float s0 = 0.0f, s1 = 0.0f;
    for (int k = lane; k < HH; k += 32) {
        float x = t2[warp * HH + k];
        s0 += x * Wm2[k];
        s1 += x * Wm2[HH + k];
    }
#pragma unroll
    for (int off = 16; off; off >>= 1) {
        s0 += __shfl_xor_sync(0xffffffffu, s0, off);
        s1 += __shfl_xor_sync(0xffffffffu, s1, off);
    }
    if (lane == 0) {
        out[((size_t)tstep * MA_ROWS + warp) * 2 + 0] = ftanh_(s0 + bm2[0]) * 0.05f;
        out[((size_t)tstep * MA_ROWS + warp) * 2 + 1] = ftanh_(s1 + bm2[1]) * 0.05f;
    }
}

// ---------------- host launcher ----------------
extern "C" void kernel_launch(void* const* d_in, const int* in_sizes, int n_in,
                              void* d_out, int out_size)
{
    const float* obs    = (const float*)d_in[0];
    const float* phys   = (const float*)d_in[1];
    const float* goals  = (const float*)d_in[2];
    const float* mem_p  = (const float*)d_in[3];
    const float* mem_a  = (const float*)d_in[4];
    const float* Wih_p  = (const float*)d_in[5];
    const float* Whh_p  = (const float*)d_in[6];
    const float* bih_p  = (const float*)d_in[7];
    const float* bhh_p  = (const float*)d_in[8];
    const float* Wfc_p  = (const float*)d_in[9];
    const float* bfc_p  = (const float*)d_in[10];
    const float* Wih_a  = (const float*)d_in[11];
    const float* Whh_a  = (const float*)d_in[12];
    const float* bih_a  = (const float*)d_in[13];
    const float* bhh_a  = (const float*)d_in[14];
    const float* Wfc_a  = (const float*)d_in[15];
    const float* bfc_a  = (const float*)d_in[16];
    const float* Wm1    = (const float*)d_in[17];
    const float* bm1    = (const float*)d_in[18];
    const float* Wm2    = (const float*)d_in[19];
    const float* bm2    = (const float*)d_in[20];
    float* out = (float*)d_out;

    void* p;
    __half *h_hi[3], *h_lo[3], *xc_hi[2], *xc_lo[2];
    cudaGetSymbolAddress(&p, g_h_hi);
    h_hi[0] = (__half*)p; h_hi[1] = h_hi[0] + (size_t)MP_ROWS*HH; h_hi[2] = h_hi[1] + (size_t)MP_ROWS*HH;
    cudaGetSymbolAddress(&p, g_h_lo);
    h_lo[0] = (__half*)p; h_lo[1] = h_lo[0] + (size_t)MP_ROWS*HH; h_lo[2] = h_lo[1] + (size_t)MP_ROWS*HH;
    cudaGetSymbolAddress(&p, g_xcat_hi); xc_hi[0] = (__half*)p; xc_hi[1] = xc_hi[0] + (size_t)MA_ROWS*512;
    cudaGetSymbolAddress(&p, g_xcat_lo); xc_lo[0] = (__half*)p; xc_lo[1] = xc_lo[0] + (size_t)MA_ROWS*512;
    cudaGetSymbolAddress(&p, g_proc_hi); __half* proc_hi = (__half*)p;
    cudaGetSymbolAddress(&p, g_t1_hi);   __half* t1_hi = (__half*)p;
    cudaGetSymbolAddress(&p, g_t2);      float* t2 = (float*)p;
    cudaGetSymbolAddress(&p, g_xp8);     float* xp8 = (float*)p;
    cudaGetSymbolAddress(&p, g_xa4);     float* xa4 = (float*)p;
    cudaGetSymbolAddress(&p, g_Wp8);     float* Wp8 = (float*)p;
    cudaGetSymbolAddress(&p, g_Wa8);     float* Wa8 = (float*)p;
    cudaGetSymbolAddress(&p, g_Whhp);    __half* Whhp = (__half*)p;
    cudaGetSymbolAddress(&p, g_Wfcp);    __half* Wfcp = (__half*)p;
    cudaGetSymbolAddress(&p, g_Wcat);    __half* Wcat = (__half*)p;
    cudaGetSymbolAddress(&p, g_Wfca);    __half* Wfca = (__half*)p;
    cudaGetSymbolAddress(&p, g_Wm1);     __half* Wm1h = (__half*)p;

    const int SM_0_128 = (2*128*72 + 2*3*64*72) * 2;   // 92160
    const int SM_1_64  = (2*64*72  + 2*4*64*72) * 2;   // 92160
    const int SM_2_128 = (2*128*72 + 2*1*64*72) * 2;   // 55296
    const int SM_2_64  = (2*64*72  + 2*1*64*72) * 2;   // 36864
    cudaFuncSetAttribute((const void*)fused_kernel<0,128>, cudaFuncAttributeMaxDynamicSharedMemorySize, SM_0_128);
    cudaFuncSetAttribute((const void*)fused_kernel<1,64>,  cudaFuncAttributeMaxDynamicSharedMemorySize, SM_1_64);
    cudaFuncSetAttribute((const void*)fused_kernel<2,128>, cudaFuncAttributeMaxDynamicSharedMemorySize, SM_2_128);
    cudaFuncSetAttribute((const void*)fused_kernel<2,64>,  cudaFuncAttributeMaxDynamicSharedMemorySize, SM_2_64);

    // ---- one-time stream/event setup ----
    static cudaStream_t sA = nullptr, sB = nullptr;
    static cudaEvent_t evFork = nullptr, evJoinA = nullptr, evJoinB = nullptr;
    static cudaEvent_t evG[TT], evF[TT], evP[TT], evA[TT];
    if (sA == nullptr) {
        cudaStreamCreateWithFlags(&sA, cudaStreamNonBlocking);
        cudaStreamCreateWithFlags(&sB, cudaStreamNonBlocking);
        cudaEventCreateWithFlags(&evFork, cudaEventDisableTiming);
        cudaEventCreateWithFlags(&evJoinA, cudaEventDisableTiming);
        cudaEventCreateWithFlags(&evJoinB, cudaEventDisableTiming);
        for (int i = 0; i < TT; i++) {
            cudaEventCreateWithFlags(&evG[i], cudaEventDisableTiming);
            cudaEventCreateWithFlags(&evF[i], cudaEventDisableTiming);
            cudaEventCreateWithFlags(&evP[i], cudaEventDisableTiming);
            cudaEventCreateWithFlags(&evA[i], cudaEventDisableTiming);
        }
    }

    cudaStream_t s0 = 0;

    // ---- fork sB immediately so its prep work is rooted in the capture ----
    cudaEventRecord(evFork, s0);
    cudaStreamWaitEvent(sB, evFork, 0);

    // ---- gru_p-critical prep on s0 ----
    split_kernel<<<(MP_ROWS*HH + 255)/256, 256, 0, s0>>>(mem_p, h_hi[0], h_lo[0], MP_ROWS*HH);
    conv_kernel<<<(G3H*HH + 255)/256, 256, 0, s0>>>(Whh_p, Whhp, G3H*HH);
    prep_xp_kernel<<<(MP_ROWS + 255)/256, 256, 0, s0>>>(obs, phys, xp8);
    prep_wp8_kernel<<<(G3H + 255)/256, 256, 0, s0>>>(Wih_p, bih_p, bhh_p, Wp8);

    // ---- everything else on sB (hides under gru_p(0)) ----
    split_strided_kernel<<<(MA_ROWS*HH + 255)/256, 256, 0, sB>>>(mem_a, xc_hi[0] + 256, xc_lo[0] + 256, MA_ROWS, HH, 512);
    conv_kernel<<<(HH*HH + 255)/256, 256, 0, sB>>>(Wfc_p, Wfcp, HH*HH);
    conv_kernel<<<(HH*HH + 255)/256, 256, 0, sB>>>(Wfc_a, Wfca, HH*HH);
    conv_kernel<<<(HH*HH + 255)/256, 256, 0, sB>>>(Wm1, Wm1h, HH*HH);
    build_wcat_kernel<<<(1024*512 + 255)/256, 256, 0, sB>>>(Wih_a, Whh_a, Wcat);
    prep_xa_kernel<<<(MA_ROWS + 255)/256, 256, 0, sB>>>(goals, xa4);
    prep_wa8_kernel<<<(G3H + 255)/256, 256, 0, sB>>>(Wih_a, bih_a, bhh_a, Wa8);

    // ---- recurrence ----
    // s0 : gru_p chain (critical path). sB : fc_p + pool. sA : action chain.
    // h triple-buffered: gru_p(t) reads h[t%3], writes h[(t+1)%3]; WAR -> wait evF[t-3].
    for (int t = 0; t < TT; t++) {
        int cur = t % 3;
        int nxt = (t + 1) % 3;
        int xc = t & 1, xn = (t + 1) & 1;
        // ---- physical GRU on s0 ----
        if (t >= 3) cudaStreamWaitEvent(s0, evF[t - 3], 0);
        fused_kernel<0,128><<<dim3(MP_ROWS/128, 4), 256, SM_0_128, s0>>>(
            h_hi[cur], HH, Whhp, xp8, Wp8,
            h_hi[cur], h_lo[cur], HH,
            h_hi[nxt], h_lo[nxt], HH, nullptr);
        cudaEventRecord(evG[t], s0);

        // ---- fc_p + pool on sB ----
        cudaStreamWaitEvent(sB, evG[t], 0);
        fused_kernel<2,128><<<dim3(MP_ROWS/128, 4), 256, SM_2_128, sB>>>(
            h_hi[nxt], HH, Wfcp, bfc_p, nullptr,
            nullptr, nullptr, 0,
            proc_hi, nullptr, HH, nullptr);
        cudaEventRecord(evF[t], sB);
        if (t >= 2) cudaStreamWaitEvent(sB, evA[t - 2], 0);
        pool_kernel<<<(MA_ROWS*32 + 255)/256, 256, 0, sB>>>(proc_hi, xc_hi[xc]);
        cudaEventRecord(evP[t], sB);

        // ---- action chain on sA ----
        cudaStreamWaitEvent(sA, evP[t], 0);
        fused_kernel<1,64><<<dim3(MA_ROWS/64, 4), 256, SM_1_64, sA>>>(
            xc_hi[xc], 512, Wcat, xa4, Wa8,
            xc_hi[xc] + 256, xc_lo[xc] + 256, 512,
            xc_hi[xn] + 256, xc_lo[xn] + 256, 512, nullptr);
        cudaEventRecord(evA[t], sA);
        fused_kernel<2,64><<<dim3(MA_ROWS/64, 4), 256, SM_2_64, sA>>>(
            xc_hi[xn] + 256, 512, Wfca, bfc_a, nullptr,
            nullptr, nullptr, 0,
            t1_hi, nullptr, HH, nullptr);
        fused_kernel<2,64><<<dim3(MA_ROWS/64, 4), 256, SM_2_64, sA>>>(
            t1_hi, HH, Wm1h, bm1, nullptr,
            nullptr, nullptr, 0,
            nullptr, nullptr, 0, t2);
        head_kernel<<<(MA_ROWS*32 + 255)/256, 256, 0, sA>>>(t2, Wm2, bm2, out, t);
    }

    // join side streams back into stream 0
    cudaEventRecord(evJoinA, sA);
    cudaStreamWaitEvent(s0, evJoinA, 0);
    cudaEventRecord(evJoinB, sB);
    cudaStreamWaitEvent(s0, evJoinB, 0);
}

// round 16
// speedup vs baseline: 1.1719x; 1.0204x over previous
#include <cuda_runtime.h>
#include <cuda_fp16.h>
#include <mma.h>
#include <math.h>
#include <stdint.h>

using namespace nvcuda;

#define BB 512
#define AA 4
#define EE 10
#define HH 256
#define TT 10
#define MP_ROWS (BB*AA*EE)   // 20480
#define MA_ROWS (BB*AA)      // 2048
#define G3H (3*HH)           // 768

// ---------------- scratch ----------------
__device__ __half g_h_hi[3][MP_ROWS * HH];
__device__ __half g_h_lo[3][MP_ROWS * HH];
__device__ __half g_xcat_hi[2][MA_ROWS * 512];   // [feat | ma]
__device__ __half g_xcat_lo[2][MA_ROWS * 512];
__device__ __half g_proc_hi[MP_ROWS * HH];
__device__ __half g_t1_hi[MA_ROWS * HH];
__device__ float g_t2[MA_ROWS * HH];
__device__ float g_xp8[MP_ROWS * 8];     // [ob0,ob1,ph0,ph1,ph2,0,0,0]
__device__ float g_xa4[MA_ROWS * 4];     // [g0,g1,g2,0]
__device__ float g_Wp8[G3H * 8];         // [w0..w4, bih, bhh, 0]
__device__ float g_Wa8[G3H * 8];         // [wg0..2, bih, bhh, 0,0,0]
__device__ __half g_Whhp[G3H * HH];
__device__ __half g_Wfcp[HH * HH];
__device__ __half g_Wcat[1024 * 512];
__device__ __half g_Wfca[HH * HH];
__device__ __half g_Wm1[HH * HH];

// ---------------- helpers ----------------
__device__ __forceinline__ float fsig(float x) {
    float e = __expf(-x);
    return __fdividef(1.0f, 1.0f + e);
}
__device__ __forceinline__ float ftanh_(float x) {
    float xc = fmaxf(fminf(x, 15.0f), -15.0f);
    float e = __expf(-2.0f * xc);
    return __fdividef(1.0f - e, 1.0f + e);
}
__device__ __forceinline__ float eluf_(float x) { return x > 0.0f ? x : expm1f(x); }
__device__ __forceinline__ void split_fp16(float x, __half& hi, __half& lo) {
    hi = __float2half_rn(x);
    lo = __float2half_rn(x - __half2float(hi));
}
__device__ __forceinline__ void cp16(void* dst, const void* src) {
    unsigned d = (unsigned)__cvta_generic_to_shared(dst);
    asm volatile("cp.async.cg.shared.global [%0], [%1], 16;\n" :: "r"(d), "l"(src));
}
__device__ __forceinline__ void cp_commit() { asm volatile("cp.async.commit_group;\n" ::); }
template<int N> __device__ __forceinline__ void cp_wait() { asm volatile("cp.async.wait_group %0;\n" :: "n"(N)); }

// ---------------- prep kernels ----------------
__global__ void prep_xp_kernel(const float* __restrict__ obs, const float* __restrict__ phys,
                               float* __restrict__ xp8)
{
    int r = blockIdx.x * blockDim.x + threadIdx.x;
    if (r >= MP_ROWS) return;
    int b = r / (AA*EE);
    int e = r % EE;
    float* o = xp8 + r * 8;
    o[0] = obs[r*2+0]; o[1] = obs[r*2+1];
    const float* ph = phys + (b * EE + e) * 3;
    o[2] = ph[0]; o[3] = ph[1]; o[4] = ph[2];
    o[5] = 0.f; o[6] = 0.f; o[7] = 0.f;
}
__global__ void prep_wp8_kernel(const float* __restrict__ Wih, const float* __restrict__ bih,
                                const float* __restrict__ bhh, float* __restrict__ Wp8)
{
    int r = blockIdx.x * blockDim.x + threadIdx.x;
    if (r >= G3H) return;
    float* o = Wp8 + r * 8;
#pragma unroll
    for (int k = 0; k < 5; k++) o[k] = Wih[r*5+k];
    o[5] = bih[r]; o[6] = bhh[r]; o[7] = 0.f;
}
__global__ void prep_xa_kernel(const float* __restrict__ goals, float* __restrict__ xa4)
{
    int m = blockIdx.x * blockDim.x + threadIdx.x;
    if (m >= MA_ROWS) return;
    float* o = xa4 + m * 4;
    o[0] = goals[m*3+0]; o[1] = goals[m*3+1]; o[2] = goals[m*3+2]; o[3] = 0.f;
}
__global__ void prep_wa8_kernel(const float* __restrict__ Wih, const float* __restrict__ bih,
                                const float* __restrict__ bhh, float* __restrict__ Wa8)
{
    int r = blockIdx.x * blockDim.x + threadIdx.x;
    if (r >= G3H) return;
    float* o = Wa8 + r * 8;
    o[0] = Wih[r*259+256]; o[1] = Wih[r*259+257]; o[2] = Wih[r*259+258];
    o[3] = bih[r]; o[4] = bhh[r]; o[5] = 0.f; o[6] = 0.f; o[7] = 0.f;
}
__global__ void split_kernel(const float* __restrict__ src,
                             __half* __restrict__ hi, __half* __restrict__ lo, int n)
{
    int i = blockIdx.x * blockDim.x + threadIdx.x;
    if (i >= n) return;
    split_fp16(src[i], hi[i], lo[i]);
}
__global__ void split_strided_kernel(const float* __restrict__ src,
                                     __half* __restrict__ hi, __half* __restrict__ lo,
                                     int rows, int cols, int ldo)
{
    int i = blockIdx.x * blockDim.x + threadIdx.x;
    if (i >= rows * cols) return;
    int r = i / cols, c = i - r * cols;
    split_fp16(src[i], hi[r * ldo + c], lo[r * ldo + c]);
}
__global__ void conv_kernel(const float* __restrict__ src, __half* __restrict__ dst, int n)
{
    int i = blockIdx.x * blockDim.x + threadIdx.x;
    if (i >= n) return;
    dst[i] = __float2half_rn(src[i]);
}
// Wcat [1024, 512]: rows g*256+n. g=0:[Wih_r|Whh_r] g=1:[Wih_z|Whh_z] g=2:[Wih_n|0] g=3:[0|Whh_n]
__global__ void build_wcat_kernel(const float* __restrict__ Wih,  // [768,259]
                                  const float* __restrict__ Whh,  // [768,256]
                                  __half* __restrict__ Wcat)
{
    int idx = blockIdx.x * blockDim.x + threadIdx.x;
    if (idx >= 1024 * 512) return;
    int row = idx >> 9, col = idx & 511;
    int g = row >> 8, n = row & 255;
    float v = 0.0f;
    if (g < 2) {
        v = (col < 256) ? Wih[(g * 256 + n) * 259 + col] : Whh[(g * 256 + n) * 256 + (col - 256)];
    } else if (g == 2) {
        if (col < 256) v = Wih[(512 + n) * 259 + col];
    } else {
        if (col >= 256) v = Whh[(512 + n) * 256 + (col - 256)];
    }
    Wcat[idx] = __float2half_rn(v);
}

// ---------------- fused fp16 single-pass GEMM kernel (BK=64, 3-stage, single-sync) ----------------
// MODE 0: physical GRU  (NSEG=3, K=256), MODE 1: action GRU (NSEG=4, K=512),
// MODE 2: ELU layer     (NSEG=1, K=256).
// 3 smem buffers (tile t -> buf t%3): load for kt+2 targets the buffer freed by
// the start-of-iteration sync, so the post-compute sync is removed.
template<int MODE, int BM>
__global__ __launch_bounds__(256) void fused_kernel(
    const __half* __restrict__ Ahi, int lda,
    const __half* __restrict__ B,
    const float* __restrict__ xw,     // xp8 / xa4 / bias
    const float* __restrict__ swg,    // Wp8 / Wa8 / unused
    const __half* __restrict__ oldHi, const __half* __restrict__ oldLo, int oldLd,
    __half* __restrict__ Ohi, __half* __restrict__ Olo, int ldo,
    float* __restrict__ Ofp)
{
    constexpr int NSEG = (MODE == 0) ? 3 : ((MODE == 1) ? 4 : 1);
    constexpr int K = (MODE == 1) ? 512 : 256;
    constexpr int KT = K / 64;
    constexpr int WN = (MODE == 2) ? 2 : 4;       // warps along n
    constexpr int WM = 8 / WN;                    // warps along m
    constexpr int MI = BM / WM / 16;
    constexpr int NJ = 64 / WN / 16;
    constexpr int STR = 72;
    constexpr int AITER = BM / 32;
    constexpr int AHS = BM * STR;
    constexpr int BHS = NSEG * 64 * STR;

    extern __shared__ __align__(16) char smem_raw[];
    __half* sm = (__half*)smem_raw;
    __half* sAh[3] = { sm, sm + AHS, sm + 2*AHS };
    __half* sB[3]  = { sm + 3*AHS, sm + 3*AHS + BHS, sm + 3*AHS + 2*BHS };

    const int m0 = blockIdx.x * BM;
    const int n0 = blockIdx.y * 64;
    const int tid = threadIdx.x;
    const int wid = tid >> 5;
    const int lane = tid & 31;
    const int wm = wid / WN, wn = wid % WN;

    auto load_tile = [&](int s, int kt) {
        const int k0 = kt * 64;
#pragma unroll
        for (int r = 0; r < AITER; r++) {
            int c = tid + r * 256;
            int row = c >> 3, kk = (c & 7) * 8;
            cp16(sAh[s] + row * STR + kk, Ahi + (size_t)(m0 + row) * lda + k0 + kk);
        }
#pragma unroll
        for (int r = 0; r < NSEG * 2; r++) {
            int c = tid + r * 256;
            int srow = c >> 3, kk = (c & 7) * 8;
            if (MODE == 1) {
                int seg = srow >> 6;
                if ((seg == 2 && kt >= 4) || (seg == 3 && kt < 4)) continue;
            }
            int srcrow = (MODE == 2) ? (n0 + srow) : ((srow >> 6) * 256 + n0 + (srow & 63));
            cp16(sB[s] + srow * STR + kk, B + (size_t)srcrow * K + k0 + kk);
        }
    };

    wmma::fragment<wmma::accumulator, 16, 16, 16, float> acc[NSEG][MI][NJ];
#pragma unroll
    for (int g = 0; g < NSEG; g++)
#pragma unroll
        for (int i = 0; i < MI; i++)
#pragma unroll
            for (int j = 0; j < NJ; j++) wmma::fill_fragment(acc[g][i][j], 0.0f);

    load_tile(0, 0); cp_commit();
    load_tile(1, 1); cp_commit();

    for (int kt = 0; kt < KT; kt++) {
        if (kt == KT - 1) cp_wait<0>(); else cp_wait<1>();
        __syncthreads();                              // tile kt visible; buf (kt+2)%3 free
        if (kt + 2 < KT) { load_tile((kt + 2) % 3, kt + 2); cp_commit(); }
        const int s = kt % 3;
        const bool featHalf = (MODE != 1) || (kt < 4);
#pragma unroll
        for (int kc = 0; kc < 64; kc += 16) {
            wmma::fragment<wmma::matrix_a, 16, 16, 16, __half, wmma::row_major> ah[MI];
#pragma unroll
            for (int i = 0; i < MI; i++)
                wmma::load_matrix_sync(ah[i], sAh[s] + (wm * 16 * MI + i * 16) * STR + kc, STR);
#pragma unroll
            for (int g = 0; g < NSEG; g++) {
                if (MODE == 1) {
                    if ((g == 2 && !featHalf) || (g == 3 && featHalf)) continue;
                }
                wmma::fragment<wmma::matrix_b, 16, 16, 16, __half, wmma::col_major> b[NJ];
#pragma unroll
                for (int j = 0; j < NJ; j++)
                    wmma::load_matrix_sync(b[j], sB[s] + (g * 64 + (wn * NJ + j) * 16) * STR + kc, STR);
#pragma unroll
                for (int i = 0; i < MI; i++)
#pragma unroll
                    for (int j = 0; j < NJ; j++)
                        wmma::mma_sync(acc[g][i][j], ah[i], b[j], acc[g][i][j]);
            }
        }
    }
    __syncthreads();   // all compute done before smem reuse

    // ---------------- epilogue ----------------
    float* wbuf = (float*)smem_raw;
    float* sX = wbuf + 8 * NSEG * 320;
    constexpr int XW = (MODE == 1) ? 4 : 8;
    float* sW = sX + BM * XW;

    if (MODE != 2) {
#pragma unroll
        for (int r = 0; r < (BM * XW + 255) / 256; r++) {
            int c = tid + r * 256;
            if (c < BM * XW) sX[c] = xw[(size_t)(m0 + (c / XW)) * XW + (c % XW)];
        }
#pragma unroll
        for (int r = 0; r < 6; r++) {
            int c = tid + r * 256;
            int srow = c >> 3, k = c & 7;
            sW[c] = swg[(size_t)((srow >> 6) * 256 + n0 + (srow & 63)) * 8 + k];
        }
    }
    __syncthreads();

    float* wb = wbuf + wid * NSEG * 320;
    const int r_ = lane >> 1;
    const int c0_ = (lane & 1) * 8;

#pragma unroll
    for (int i = 0; i < MI; i++) {
#pragma unroll
        for (int j = 0; j < NJ; j++) {
#pragma unroll
            for (int g = 0; g < NSEG; g++)
                wmma::store_matrix_sync(wb + g * 320, acc[g][i][j], 20, wmma::mem_row_major);
            __syncwarp();

            const int mloc = wm * 16 * MI + i * 16 + r_;
            const int m = m0 + mloc;
            const int nl0 = (wn * NJ + j) * 16 + c0_;
            const int nabs = n0 + nl0;

            __half oh8[8], ol8[8];

            if (MODE == 2) {
                float4 b0 = *(const float4*)&xw[nabs];
                float4 b1 = *(const float4*)&xw[nabs + 4];
                float bia[8] = {b0.x,b0.y,b0.z,b0.w,b1.x,b1.y,b1.z,b1.w};
                float ov[8];
#pragma unroll
                for (int cc = 0; cc < 8; cc++) {
                    float v = eluf_(wb[r_ * 20 + c0_ + cc] + bia[cc]);
                    ov[cc] = v;
                    oh8[cc] = __float2half_rn(v);
                }
                if (Ofp) {
                    *(float4*)&Ofp[(size_t)m * 256 + nabs] = make_float4(ov[0],ov[1],ov[2],ov[3]);
                    *(float4*)&Ofp[(size_t)m * 256 + nabs + 4] = make_float4(ov[4],ov[5],ov[6],ov[7]);
                }
                if (Ohi) {
                    *(uint4*)&Ohi[(size_t)m * ldo + nabs] = *(uint4*)oh8;
                }
            } else {
                uint4 hv4 = *(const uint4*)&oldHi[(size_t)m * oldLd + nabs];
                uint4 lv4 = *(const uint4*)&oldLo[(size_t)m * oldLd + nabs];
                const __half* hvp = (const __half*)&hv4;
                const __half* lvp = (const __half*)&lv4;
                float xr[XW];
#pragma unroll
                for (int k = 0; k < XW; k++) xr[k] = sX[mloc * XW + k];
#pragma unroll
                for (int cc = 0; cc < 8; cc++) {
                    int nl = nl0 + cc;
                    const float* w0 = sW + (0 * 64 + nl) * 8;
                    const float* w1 = sW + (1 * 64 + nl) * 8;
                    const float* w2 = sW + (2 * 64 + nl) * 8;
                    float a0 = wb[0 * 320 + r_ * 20 + c0_ + cc];
                    float a1 = wb[1 * 320 + r_ * 20 + c0_ + cc];
                    float a2 = wb[2 * 320 + r_ * 20 + c0_ + cc];
                    float gi_r, gi_z, gi_n, rr, zz, nn;
                    if (MODE == 0) {
                        gi_r = w0[5]; gi_z = w1[5]; gi_n = w2[5];
#pragma unroll
                        for (int k = 0; k < 5; k++) {
                            gi_r += xr[k] * w0[k];
                            gi_z += xr[k] * w1[k];
                            gi_n += xr[k] * w2[k];
                        }
                        rr = fsig(gi_r + a0 + w0[6]);
                        zz = fsig(gi_z + a1 + w1[6]);
                        nn = ftanh_(gi_n + rr * (a2 + w2[6]));
                    } else {
                        float a3 = wb[3 * 320 + r_ * 20 + c0_ + cc];
                        gi_r = w0[3]; gi_z = w1[3]; gi_n = w2[3];
#pragma unroll
                        for (int k = 0; k < 3; k++) {
                            gi_r += xr[k] * w0[k];
                            gi_z += xr[k] * w1[k];
                            gi_n += xr[k] * w2[k];
                        }
                        rr = fsig(gi_r + a0 + w0[4]);
                        zz = fsig(gi_z + a1 + w1[4]);
                        nn = ftanh_(gi_n + a2 + rr * (a3 + w2[4]));
                    }
                    float hold = __half2float(hvp[cc]) + __half2float(lvp[cc]);
                    float hnew = (1.0f - zz) * nn + zz * hold;
                    split_fp16(hnew, oh8[cc], ol8[cc]);
                }
                *(uint4*)&Ohi[(size_t)m * ldo + nabs] = *(uint4*)oh8;
                *(uint4*)&Olo[(size_t)m * ldo + nabs] = *(uint4*)ol8;
            }
            __syncwarp();
        }
    }
}

// ---------------- entity max-pool (hi planes only) ----------------
__global__ void pool_kernel(const __half* __restrict__ phi,
                            __half* __restrict__ xcat_hi)
{
    int idx = blockIdx.x * blockDim.x + threadIdx.x;
    if (idx >= MA_ROWS * 32) return;
    int m = idx >> 5, c8 = (idx & 31) * 8;
    float v[8];
#pragma unroll
    for (int k = 0; k < 8; k++) v[k] = -1e30f;
#pragma unroll
    for (int e = 0; e < EE; e++) {
        size_t off = (size_t)(m * EE + e) * HH + c8;
        uint4 h4 = *(const uint4*)&phi[off];
        const __half* hp = (const __half*)&h4;
#pragma unroll
        for (int k = 0; k < 8; k++)
            v[k] = fmaxf(v[k], __half2float(hp[k]));
    }
    __half h8[8];
#pragma unroll
    for (int k = 0; k < 8; k++) h8[k] = __float2half_rn(v[k]);
    *(uint4*)&xcat_hi[(size_t)m * 512 + c8] = *(uint4*)h8;
}

// ---------------- head ----------------
__global__ void head_kernel(const float* __restrict__ t2,
                            const float* __restrict__ Wm2, const float* __restrict__ bm2,
                            float* __restrict__ out, int tstep)
{
    int warp = (blockIdx.x * blockDim.x + threadIdx.x) >> 5;
    int lane = threadIdx.x & 31;
    if (warp >= MA_ROWS) return;
    float s0 = 0.0f, s1 = 0.0f;
    for (int k = lane; k < HH; k += 32) {
        float x = t2[warp * HH + k];
        s0 += x * Wm2[k];
        s1 += x * Wm2[HH + k];
    }
#pragma unroll
    for (int off = 16; off; off >>= 1) {
        s0 += __shfl_xor_sync(0xffffffffu, s0, off);
        s1 += __shfl_xor_sync(0xffffffffu, s1, off);
    }
    if (lane == 0) {
        out[((size_t)tstep * MA_ROWS + warp) * 2 + 0] = ftanh_(s0 + bm2[0]) * 0.05f;
        out[((size_t)tstep * MA_ROWS + warp) * 2 + 1] = ftanh_(s1 + bm2[1]) * 0.05f;
    }
}

// ---------------- host launcher ----------------
extern "C" void kernel_launch(void* const* d_in, const int* in_sizes, int n_in,
                              void* d_out, int out_size)
{
    const float* obs    = (const float*)d_in[0];
    const float* phys   = (const float*)d_in[1];
    const float* goals  = (const float*)d_in[2];
    const float* mem_p  = (const float*)d_in[3];
    const float* mem_a  = (const float*)d_in[4];
    const float* Wih_p  = (const float*)d_in[5];
    const float* Whh_p  = (const float*)d_in[6];
    const float* bih_p  = (const float*)d_in[7];
    const float* bhh_p  = (const float*)d_in[8];
    const float* Wfc_p  = (const float*)d_in[9];
    const float* bfc_p  = (const float*)d_in[10];
    const float* Wih_a  = (const float*)d_in[11];
    const float* Whh_a  = (const float*)d_in[12];
    const float* bih_a  = (const float*)d_in[13];
    const float* bhh_a  = (const float*)d_in[14];
    const float* Wfc_a  = (const float*)d_in[15];
    const float* bfc_a  = (const float*)d_in[16];
    const float* Wm1    = (const float*)d_in[17];
    const float* bm1    = (const float*)d_in[18];
    const float* Wm2    = (const float*)d_in[19];
    const float* bm2    = (const float*)d_in[20];
    float* out = (float*)d_out;

    void* p;
    __half *h_hi[3], *h_lo[3], *xc_hi[2], *xc_lo[2];
    cudaGetSymbolAddress(&p, g_h_hi);
    h_hi[0] = (__half*)p; h_hi[1] = h_hi[0] + (size_t)MP_ROWS*HH; h_hi[2] = h_hi[1] + (size_t)MP_ROWS*HH;
    cudaGetSymbolAddress(&p, g_h_lo);
    h_lo[0] = (__half*)p; h_lo[1] = h_lo[0] + (size_t)MP_ROWS*HH; h_lo[2] = h_lo[1] + (size_t)MP_ROWS*HH;
    cudaGetSymbolAddress(&p, g_xcat_hi); xc_hi[0] = (__half*)p; xc_hi[1] = xc_hi[0] + (size_t)MA_ROWS*512;
    cudaGetSymbolAddress(&p, g_xcat_lo); xc_lo[0] = (__half*)p; xc_lo[1] = xc_lo[0] + (size_t)MA_ROWS*512;
    cudaGetSymbolAddress(&p, g_proc_hi); __half* proc_hi = (__half*)p;
    cudaGetSymbolAddress(&p, g_t1_hi);   __half* t1_hi = (__half*)p;
    cudaGetSymbolAddress(&p, g_t2);      float* t2 = (float*)p;
    cudaGetSymbolAddress(&p, g_xp8);     float* xp8 = (float*)p;
    cudaGetSymbolAddress(&p, g_xa4);     float* xa4 = (float*)p;
    cudaGetSymbolAddress(&p, g_Wp8);     float* Wp8 = (float*)p;
    cudaGetSymbolAddress(&p, g_Wa8);     float* Wa8 = (float*)p;
    cudaGetSymbolAddress(&p, g_Whhp);    __half* Whhp = (__half*)p;
    cudaGetSymbolAddress(&p, g_Wfcp);    __half* Wfcp = (__half*)p;
    cudaGetSymbolAddress(&p, g_Wcat);    __half* Wcat = (__half*)p;
    cudaGetSymbolAddress(&p, g_Wfca);    __half* Wfca = (__half*)p;
    cudaGetSymbolAddress(&p, g_Wm1);     __half* Wm1h = (__half*)p;

    // 3-stage smem: 3*(BM + NSEG*64)*72*2 bytes
    const int SM_0_128 = 3 * (128 + 192) * 72 * 2;   // 138240
    const int SM_1_64  = 3 * (64 + 256) * 72 * 2;    // 138240
    const int SM_2_128 = 3 * (128 + 64) * 72 * 2;    // 82944
    const int SM_2_64  = 3 * (64 + 64) * 72 * 2;     // 55296
    cudaFuncSetAttribute((const void*)fused_kernel<0,128>, cudaFuncAttributeMaxDynamicSharedMemorySize, SM_0_128);
    cudaFuncSetAttribute((const void*)fused_kernel<1,64>,  cudaFuncAttributeMaxDynamicSharedMemorySize, SM_1_64);
    cudaFuncSetAttribute((const void*)fused_kernel<2,128>, cudaFuncAttributeMaxDynamicSharedMemorySize, SM_2_128);
    cudaFuncSetAttribute((const void*)fused_kernel<2,64>,  cudaFuncAttributeMaxDynamicSharedMemorySize, SM_2_64);

    // ---- one-time stream/event setup ----
    static cudaStream_t sA = nullptr, sB = nullptr;
    static cudaEvent_t evFork = nullptr, evPrep = nullptr, evJoinA = nullptr, evJoinB = nullptr;
    static cudaEvent_t evG[TT], evF[TT], evP[TT], evA[TT];
    if (sA == nullptr) {
        cudaStreamCreateWithFlags(&sA, cudaStreamNonBlocking);
        cudaStreamCreateWithFlags(&sB, cudaStreamNonBlocking);
        cudaEventCreateWithFlags(&evFork, cudaEventDisableTiming);
        cudaEventCreateWithFlags(&evPrep, cudaEventDisableTiming);
        cudaEventCreateWithFlags(&evJoinA, cudaEventDisableTiming);
        cudaEventCreateWithFlags(&evJoinB, cudaEventDisableTiming);
        for (int i = 0; i < TT; i++) {
            cudaEventCreateWithFlags(&evG[i], cudaEventDisableTiming);
            cudaEventCreateWithFlags(&evF[i], cudaEventDisableTiming);
            cudaEventCreateWithFlags(&evP[i], cudaEventDisableTiming);
            cudaEventCreateWithFlags(&evA[i], cudaEventDisableTiming);
        }
    }

    cudaStream_t s0 = 0;

    // ---- fork sB immediately ----
    cudaEventRecord(evFork, s0);
    cudaStreamWaitEvent(sB, evFork, 0);

    // ---- prep: big h-split on s0; small gru_p-critical preps on sB (overlap) ----
    split_kernel<<<(MP_ROWS*HH + 255)/256, 256, 0, s0>>>(mem_p, h_hi[0], h_lo[0], MP_ROWS*HH);
    conv_kernel<<<(G3H*HH + 255)/256, 256, 0, sB>>>(Whh_p, Whhp, G3H*HH);
    prep_xp_kernel<<<(MP_ROWS + 255)/256, 256, 0, sB>>>(obs, phys, xp8);
    prep_wp8_kernel<<<(G3H + 255)/256, 256, 0, sB>>>(Wih_p, bih_p, bhh_p, Wp8);
    cudaEventRecord(evPrep, sB);
    cudaStreamWaitEvent(s0, evPrep, 0);   // gru_p(0) needs Whhp/xp8/Wp8

    // ---- remaining prep on sB (hides under gru_p(0)) ----
    split_strided_kernel<<<(MA_ROWS*HH + 255)/256, 256, 0, sB>>>(mem_a, xc_hi[0] + 256, xc_lo[0] + 256, MA_ROWS, HH, 512);
    conv_kernel<<<(HH*HH + 255)/256, 256, 0, sB>>>(Wfc_p, Wfcp, HH*HH);
    conv_kernel<<<(HH*HH + 255)/256, 256, 0, sB>>>(Wfc_a, Wfca, HH*HH);
    conv_kernel<<<(HH*HH + 255)/256, 256, 0, sB>>>(Wm1, Wm1h, HH*HH);
    build_wcat_kernel<<<(1024*512 + 255)/256, 256, 0, sB>>>(Wih_a, Whh_a, Wcat);
    prep_xa_kernel<<<(MA_ROWS + 255)/256, 256, 0, sB>>>(goals, xa4);
    prep_wa8_kernel<<<(G3H + 255)/256, 256, 0, sB>>>(Wih_a, bih_a, bhh_a, Wa8);

    // ---- recurrence ----
    // s0 : gru_p chain (critical path). sB : fc_p + pool. sA : action chain.
    // h triple-buffered: gru_p(t) reads h[t%3], writes h[(t+1)%3]; WAR -> wait evF[t-3].
    for (int t = 0; t < TT; t++) {
        int cur = t % 3;
        int nxt = (t + 1) % 3;
        int xc = t & 1, xn = (t + 1) & 1;
        // ---- physical GRU on s0 ----
        if (t >= 3) cudaStreamWaitEvent(s0, evF[t - 3], 0);
        fused_kernel<0,128><<<dim3(MP_ROWS/128, 4), 256, SM_0_128, s0>>>(
            h_hi[cur], HH, Whhp, xp8, Wp8,
            h_hi[cur], h_lo[cur], HH,
            h_hi[nxt], h_lo[nxt], HH, nullptr);
        cudaEventRecord(evG[t], s0);

        // ---- fc_p + pool on sB ----
        cudaStreamWaitEvent(sB, evG[t], 0);
        fused_kernel<2,128><<<dim3(MP_ROWS/128, 4), 256, SM_2_128, sB>>>(
            h_hi[nxt], HH, Wfcp, bfc_p, nullptr,
            nullptr, nullptr, 0,
            proc_hi, nullptr, HH, nullptr);
        cudaEventRecord(evF[t], sB);
        if (t >= 2) cudaStreamWaitEvent(sB, evA[t - 2], 0);
        pool_kernel<<<(MA_ROWS*32 + 255)/256, 256, 0, sB>>>(proc_hi, xc_hi[xc]);
        cudaEventRecord(evP[t], sB);

        // ---- action chain on sA ----
        cudaStreamWaitEvent(sA, evP[t], 0);
        fused_kernel<1,64><<<dim3(MA_ROWS/64, 4), 256, SM_1_64, sA>>>(
            xc_hi[xc], 512, Wcat, xa4, Wa8,
            xc_hi[xc] + 256, xc_lo[xc] + 256, 512,
            xc_hi[xn] + 256, xc_lo[xn] + 256, 512, nullptr);
        cudaEventRecord(evA[t], sA);
        fused_kernel<2,64><<<dim3(MA_ROWS/64, 4), 256, SM_2_64, sA>>>(
            xc_hi[xn] + 256, 512, Wfca, bfc_a, nullptr,
            nullptr, nullptr, 0,
            t1_hi, nullptr, HH, nullptr);
        fused_kernel<2,64><<<dim3(MA_ROWS/64, 4), 256, SM_2_64, sA>>>(
            t1_hi, HH, Wm1h, bm1, nullptr,
            nullptr, nullptr, 0,
            nullptr, nullptr, 0, t2);
        head_kernel<<<(MA_ROWS*32 + 255)/256, 256, 0, sA>>>(t2, Wm2, bm2, out, t);
    }

    // join side streams back into stream 0
    cudaEventRecord(evJoinA, sA);
    cudaStreamWaitEvent(s0, evJoinA, 0);
    cudaEventRecord(evJoinB, sB);
    cudaStreamWaitEvent(s0, evJoinB, 0);
}

// round 17
// speedup vs baseline: 1.1721x; 1.0002x over previous
#include <cuda_runtime.h>
#include <cuda_fp16.h>
#include <mma.h>
#include <math.h>
#include <stdint.h>

using namespace nvcuda;

#define BB 512
#define AA 4
#define EE 10
#define HH 256
#define TT 10
#define MP_ROWS (BB*AA*EE)   // 20480
#define MA_ROWS (BB*AA)      // 2048
#define G3H (3*HH)           // 768

// ---------------- scratch ----------------
__device__ __half g_h_hi[3][MP_ROWS * HH];
__device__ __half g_h_lo[3][MP_ROWS * HH];
__device__ __half g_xcat_hi[2][MA_ROWS * 512];   // [feat | ma]
__device__ __half g_xcat_lo[2][MA_ROWS * 512];
__device__ __half g_proc_hi[MP_ROWS * HH];
__device__ __half g_t1_hi[MA_ROWS * HH];
__device__ float g_t2[MA_ROWS * HH];
__device__ float g_xp8[MP_ROWS * 8];     // [ob0,ob1,ph0,ph1,ph2,0,0,0]
__device__ float g_xa4[MA_ROWS * 4];     // [g0,g1,g2,0]
__device__ float g_Wp8[G3H * 8];         // [w0..w4, bih, bhh, 0]
__device__ float g_Wa8[G3H * 8];         // [wg0..2, bih, bhh, 0,0,0]
__device__ __half g_Whhp[G3H * HH];
__device__ __half g_Wfcp[HH * HH];
__device__ __half g_Wcat[1024 * 512];
__device__ __half g_Wfca[HH * HH];
__device__ __half g_Wm1[HH * HH];

// ---------------- helpers ----------------
__device__ __forceinline__ float fsig(float x) {
    float e = __expf(-x);
    return __fdividef(1.0f, 1.0f + e);
}
__device__ __forceinline__ float ftanh_(float x) {
    float xc = fmaxf(fminf(x, 15.0f), -15.0f);
    float e = __expf(-2.0f * xc);
    return __fdividef(1.0f - e, 1.0f + e);
}
__device__ __forceinline__ float eluf_(float x) { return x > 0.0f ? x : expm1f(x); }
__device__ __forceinline__ void split_fp16(float x, __half& hi, __half& lo) {
    hi = __float2half_rn(x);
    lo = __float2half_rn(x - __half2float(hi));
}
__device__ __forceinline__ void cp16(void* dst, const void* src) {
    unsigned d = (unsigned)__cvta_generic_to_shared(dst);
    asm volatile("cp.async.cg.shared.global [%0], [%1], 16;\n" :: "r"(d), "l"(src));
}
__device__ __forceinline__ void cp_commit() { asm volatile("cp.async.commit_group;\n" ::); }
template<int N> __device__ __forceinline__ void cp_wait() { asm volatile("cp.async.wait_group %0;\n" :: "n"(N)); }

// ---------------- prep kernels ----------------
__global__ void prep_xp_kernel(const float* __restrict__ obs, const float* __restrict__ phys,
                               float* __restrict__ xp8)
{
    int r = blockIdx.x * blockDim.x + threadIdx.x;
    if (r >= MP_ROWS) return;
    int b = r / (AA*EE);
    int e = r % EE;
    float* o = xp8 + r * 8;
    o[0] = obs[r*2+0]; o[1] = obs[r*2+1];
    const float* ph = phys + (b * EE + e) * 3;
    o[2] = ph[0]; o[3] = ph[1]; o[4] = ph[2];
    o[5] = 0.f; o[6] = 0.f; o[7] = 0.f;
}
__global__ void prep_wp8_kernel(const float* __restrict__ Wih, const float* __restrict__ bih,
                                const float* __restrict__ bhh, float* __restrict__ Wp8)
{
    int r = blockIdx.x * blockDim.x + threadIdx.x;
    if (r >= G3H) return;
    float* o = Wp8 + r * 8;
#pragma unroll
    for (int k = 0; k < 5; k++) o[k] = Wih[r*5+k];
    o[5] = bih[r]; o[6] = bhh[r]; o[7] = 0.f;
}
__global__ void prep_xa_kernel(const float* __restrict__ goals, float* __restrict__ xa4)
{
    int m = blockIdx.x * blockDim.x + threadIdx.x;
    if (m >= MA_ROWS) return;
    float* o = xa4 + m * 4;
    o[0] = goals[m*3+0]; o[1] = goals[m*3+1]; o[2] = goals[m*3+2]; o[3] = 0.f;
}
__global__ void prep_wa8_kernel(const float* __restrict__ Wih, const float* __restrict__ bih,
                                const float* __restrict__ bhh, float* __restrict__ Wa8)
{
    int r = blockIdx.x * blockDim.x + threadIdx.x;
    if (r >= G3H) return;
    float* o = Wa8 + r * 8;
    o[0] = Wih[r*259+256]; o[1] = Wih[r*259+257]; o[2] = Wih[r*259+258];
    o[3] = bih[r]; o[4] = bhh[r]; o[5] = 0.f; o[6] = 0.f; o[7] = 0.f;
}
__global__ void split_kernel(const float* __restrict__ src,
                             __half* __restrict__ hi, __half* __restrict__ lo, int n)
{
    int i = blockIdx.x * blockDim.x + threadIdx.x;
    if (i >= n) return;
    split_fp16(src[i], hi[i], lo[i]);
}
__global__ void split_strided_kernel(const float* __restrict__ src,
                                     __half* __restrict__ hi, __half* __restrict__ lo,
                                     int rows, int cols, int ldo)
{
    int i = blockIdx.x * blockDim.x + threadIdx.x;
    if (i >= rows * cols) return;
    int r = i / cols, c = i - r * cols;
    split_fp16(src[i], hi[r * ldo + c], lo[r * ldo + c]);
}
__global__ void conv_kernel(const float* __restrict__ src, __half* __restrict__ dst, int n)
{
    int i = blockIdx.x * blockDim.x + threadIdx.x;
    if (i >= n) return;
    dst[i] = __float2half_rn(src[i]);
}
// Wcat [1024, 512]: rows g*256+n. g=0:[Wih_r|Whh_r] g=1:[Wih_z|Whh_z] g=2:[Wih_n|0] g=3:[0|Whh_n]
__global__ void build_wcat_kernel(const float* __restrict__ Wih,  // [768,259]
                                  const float* __restrict__ Whh,  // [768,256]
                                  __half* __restrict__ Wcat)
{
    int idx = blockIdx.x * blockDim.x + threadIdx.x;
    if (idx >= 1024 * 512) return;
    int row = idx >> 9, col = idx & 511;
    int g = row >> 8, n = row & 255;
    float v = 0.0f;
    if (g < 2) {
        v = (col < 256) ? Wih[(g * 256 + n) * 259 + col] : Whh[(g * 256 + n) * 256 + (col - 256)];
    } else if (g == 2) {
        if (col < 256) v = Wih[(512 + n) * 259 + col];
    } else {
        if (col >= 256) v = Whh[(512 + n) * 256 + (col - 256)];
    }
    Wcat[idx] = __float2half_rn(v);
}

// ---------------- fused fp16 single-pass GEMM kernel (BK=64, 3-stage, single-sync) ----------------
// MODE 0: physical GRU  (NSEG=3, K=256), MODE 1: action GRU (NSEG=4, K=512),
// MODE 2: ELU layer     (NSEG=1, K=256).
template<int MODE, int BM>
__global__ __launch_bounds__(256) void fused_kernel(
    const __half* __restrict__ Ahi, int lda,
    const __half* __restrict__ B,
    const float* __restrict__ xw,     // xp8 / xa4 / bias
    const float* __restrict__ swg,    // Wp8 / Wa8 / unused
    const __half* __restrict__ oldHi, const __half* __restrict__ oldLo, int oldLd,
    __half* __restrict__ Ohi, __half* __restrict__ Olo, int ldo,
    float* __restrict__ Ofp)
{
    constexpr int NSEG = (MODE == 0) ? 3 : ((MODE == 1) ? 4 : 1);
    constexpr int K = (MODE == 1) ? 512 : 256;
    constexpr int KT = K / 64;
    constexpr int WN = (MODE == 2) ? 2 : 4;
    constexpr int WM = 8 / WN;
    constexpr int MI = BM / WM / 16;
    constexpr int NJ = 64 / WN / 16;
    constexpr int STR = 72;
    constexpr int AITER = BM / 32;
    constexpr int AHS = BM * STR;
    constexpr int BHS = NSEG * 64 * STR;

    extern __shared__ __align__(16) char smem_raw[];
    __half* sm = (__half*)smem_raw;
    __half* sAh[3] = { sm, sm + AHS, sm + 2*AHS };
    __half* sB[3]  = { sm + 3*AHS, sm + 3*AHS + BHS, sm + 3*AHS + 2*BHS };

    const int m0 = blockIdx.x * BM;
    const int n0 = blockIdx.y * 64;
    const int tid = threadIdx.x;
    const int wid = tid >> 5;
    const int lane = tid & 31;
    const int wm = wid / WN, wn = wid % WN;

    auto load_tile = [&](int s, int kt) {
        const int k0 = kt * 64;
#pragma unroll
        for (int r = 0; r < AITER; r++) {
            int c = tid + r * 256;
            int row = c >> 3, kk = (c & 7) * 8;
            cp16(sAh[s] + row * STR + kk, Ahi + (size_t)(m0 + row) * lda + k0 + kk);
        }
#pragma unroll
        for (int r = 0; r < NSEG * 2; r++) {
            int c = tid + r * 256;
            int srow = c >> 3, kk = (c & 7) * 8;
            if (MODE == 1) {
                int seg = srow >> 6;
                if ((seg == 2 && kt >= 4) || (seg == 3 && kt < 4)) continue;
            }
            int srcrow = (MODE == 2) ? (n0 + srow) : ((srow >> 6) * 256 + n0 + (srow & 63));
            cp16(sB[s] + srow * STR + kk, B + (size_t)srcrow * K + k0 + kk);
        }
    };

    wmma::fragment<wmma::accumulator, 16, 16, 16, float> acc[NSEG][MI][NJ];
#pragma unroll
    for (int g = 0; g < NSEG; g++)
#pragma unroll
        for (int i = 0; i < MI; i++)
#pragma unroll
            for (int j = 0; j < NJ; j++) wmma::fill_fragment(acc[g][i][j], 0.0f);

    load_tile(0, 0); cp_commit();
    load_tile(1, 1); cp_commit();

    for (int kt = 0; kt < KT; kt++) {
        if (kt == KT - 1) cp_wait<0>(); else cp_wait<1>();
        __syncthreads();                              // tile kt visible; buf (kt+2)%3 free
        if (kt + 2 < KT) { load_tile((kt + 2) % 3, kt + 2); cp_commit(); }
        const int s = kt % 3;
        const bool featHalf = (MODE != 1) || (kt < 4);
#pragma unroll
        for (int kc = 0; kc < 64; kc += 16) {
            wmma::fragment<wmma::matrix_a, 16, 16, 16, __half, wmma::row_major> ah[MI];
#pragma unroll
            for (int i = 0; i < MI; i++)
                wmma::load_matrix_sync(ah[i], sAh[s] + (wm * 16 * MI + i * 16) * STR + kc, STR);
#pragma unroll
            for (int g = 0; g < NSEG; g++) {
                if (MODE == 1) {
                    if ((g == 2 && !featHalf) || (g == 3 && featHalf)) continue;
                }
                wmma::fragment<wmma::matrix_b, 16, 16, 16, __half, wmma::col_major> b[NJ];
#pragma unroll
                for (int j = 0; j < NJ; j++)
                    wmma::load_matrix_sync(b[j], sB[s] + (g * 64 + (wn * NJ + j) * 16) * STR + kc, STR);
#pragma unroll
                for (int i = 0; i < MI; i++)
#pragma unroll
                    for (int j = 0; j < NJ; j++)
                        wmma::mma_sync(acc[g][i][j], ah[i], b[j], acc[g][i][j]);
            }
        }
    }
    __syncthreads();   // all compute done before smem reuse

    // ---------------- epilogue ----------------
    float* wbuf = (float*)smem_raw;
    float* sX = wbuf + 8 * NSEG * 320;
    constexpr int XW = (MODE == 1) ? 4 : 8;
    float* sW = sX + BM * XW;

    if (MODE != 2) {
#pragma unroll
        for (int r = 0; r < (BM * XW + 255) / 256; r++) {
            int c = tid + r * 256;
            if (c < BM * XW) sX[c] = xw[(size_t)(m0 + (c / XW)) * XW + (c % XW)];
        }
#pragma unroll
        for (int r = 0; r < 6; r++) {
            int c = tid + r * 256;
            int srow = c >> 3, k = c & 7;
            sW[c] = swg[(size_t)((srow >> 6) * 256 + n0 + (srow & 63)) * 8 + k];
        }
    }
    __syncthreads();

    float* wb = wbuf + wid * NSEG * 320;
    const int r_ = lane >> 1;
    const int c0_ = (lane & 1) * 8;

#pragma unroll
    for (int i = 0; i < MI; i++) {
#pragma unroll
        for (int j = 0; j < NJ; j++) {
#pragma unroll
            for (int g = 0; g < NSEG; g++)
                wmma::store_matrix_sync(wb + g * 320, acc[g][i][j], 20, wmma::mem_row_major);
            __syncwarp();

            const int mloc = wm * 16 * MI + i * 16 + r_;
            const int m = m0 + mloc;
            const int nl0 = (wn * NJ + j) * 16 + c0_;
            const int nabs = n0 + nl0;

            __half oh8[8], ol8[8];

            if (MODE == 2) {
                float4 b0 = *(const float4*)&xw[nabs];
                float4 b1 = *(const float4*)&xw[nabs + 4];
                float bia[8] = {b0.x,b0.y,b0.z,b0.w,b1.x,b1.y,b1.z,b1.w};
                float ov[8];
#pragma unroll
                for (int cc = 0; cc < 8; cc++) {
                    float v = eluf_(wb[r_ * 20 + c0_ + cc] + bia[cc]);
                    ov[cc] = v;
                    oh8[cc] = __float2half_rn(v);
                }
                if (Ofp) {
                    *(float4*)&Ofp[(size_t)m * 256 + nabs] = make_float4(ov[0],ov[1],ov[2],ov[3]);
                    *(float4*)&Ofp[(size_t)m * 256 + nabs + 4] = make_float4(ov[4],ov[5],ov[6],ov[7]);
                }
                if (Ohi) {
                    *(uint4*)&Ohi[(size_t)m * ldo + nabs] = *(uint4*)oh8;
                }
            } else {
                uint4 hv4 = *(const uint4*)&oldHi[(size_t)m * oldLd + nabs];
                uint4 lv4 = *(const uint4*)&oldLo[(size_t)m * oldLd + nabs];
                const __half* hvp = (const __half*)&hv4;
                const __half* lvp = (const __half*)&lv4;
                float xr[XW];
#pragma unroll
                for (int k = 0; k < XW; k++) xr[k] = sX[mloc * XW + k];
#pragma unroll
                for (int cc = 0; cc < 8; cc++) {
                    int nl = nl0 + cc;
                    const float* w0 = sW + (0 * 64 + nl) * 8;
                    const float* w1 = sW + (1 * 64 + nl) * 8;
                    const float* w2 = sW + (2 * 64 + nl) * 8;
                    float a0 = wb[0 * 320 + r_ * 20 + c0_ + cc];
                    float a1 = wb[1 * 320 + r_ * 20 + c0_ + cc];
                    float a2 = wb[2 * 320 + r_ * 20 + c0_ + cc];
                    float gi_r, gi_z, gi_n, rr, zz, nn;
                    if (MODE == 0) {
                        gi_r = w0[5]; gi_z = w1[5]; gi_n = w2[5];
#pragma unroll
                        for (int k = 0; k < 5; k++) {
                            gi_r += xr[k] * w0[k];
                            gi_z += xr[k] * w1[k];
                            gi_n += xr[k] * w2[k];
                        }
                        rr = fsig(gi_r + a0 + w0[6]);
                        zz = fsig(gi_z + a1 + w1[6]);
                        nn = ftanh_(gi_n + rr * (a2 + w2[6]));
                    } else {
                        float a3 = wb[3 * 320 + r_ * 20 + c0_ + cc];
                        gi_r = w0[3]; gi_z = w1[3]; gi_n = w2[3];
#pragma unroll
                        for (int k = 0; k < 3; k++) {
                            gi_r += xr[k] * w0[k];
                            gi_z += xr[k] * w1[k];
                            gi_n += xr[k] * w2[k];
                        }
                        rr = fsig(gi_r + a0 + w0[4]);
                        zz = fsig(gi_z + a1 + w1[4]);
                        nn = ftanh_(gi_n + a2 + rr * (a3 + w2[4]));
                    }
                    float hold = __half2float(hvp[cc]) + __half2float(lvp[cc]);
                    float hnew = (1.0f - zz) * nn + zz * hold;
                    split_fp16(hnew, oh8[cc], ol8[cc]);
                }
                *(uint4*)&Ohi[(size_t)m * ldo + nabs] = *(uint4*)oh8;
                *(uint4*)&Olo[(size_t)m * ldo + nabs] = *(uint4*)ol8;
            }
            __syncwarp();
        }
    }
}

// ---------------- entity max-pool (hi planes only) ----------------
__global__ void pool_kernel(const __half* __restrict__ phi,
                            __half* __restrict__ xcat_hi)
{
    int idx = blockIdx.x * blockDim.x + threadIdx.x;
    if (idx >= MA_ROWS * 32) return;
    int m = idx >> 5, c8 = (idx & 31) * 8;
    float v[8];
#pragma unroll
    for (int k = 0; k < 8; k++) v[k] = -1e30f;
#pragma unroll
    for (int e = 0; e < EE; e++) {
        size_t off = (size_t)(m * EE + e) * HH + c8;
        uint4 h4 = *(const uint4*)&phi[off];
        const __half* hp = (const __half*)&h4;
#pragma unroll
        for (int k = 0; k < 8; k++)
            v[k] = fmaxf(v[k], __half2float(hp[k]));
    }
    __half h8[8];
#pragma unroll
    for (int k = 0; k < 8; k++) h8[k] = __float2half_rn(v[k]);
    *(uint4*)&xcat_hi[(size_t)m * 512 + c8] = *(uint4*)h8;
}

// ---------------- head ----------------
__global__ void head_kernel(const float* __restrict__ t2,
                            const float* __restrict__ Wm2, const float* __restrict__ bm2,
                            float* __restrict__ out, int tstep)
{
    int warp = (blockIdx.x * blockDim.x + threadIdx.x) >> 5;
    int lane = threadIdx.x & 31;
    if (warp >= MA_ROWS) return;
    float s0 = 0.0f, s1 = 0.0f;
    for (int k = lane; k < HH; k += 32) {
        float x = t2[warp * HH + k];
        s0 += x * Wm2[k];
        s1 += x * Wm2[HH + k];
    }
#pragma unroll
    for (int off = 16; off; off >>= 1) {
        s0 += __shfl_xor_sync(0xffffffffu, s0, off);
        s1 += __shfl_xor_sync(0xffffffffu, s1, off);
    }
    if (lane == 0) {
        out[((size_t)tstep * MA_ROWS + warp) * 2 + 0] = ftanh_(s0 + bm2[0]) * 0.05f;
        out[((size_t)tstep * MA_ROWS + warp) * 2 + 1] = ftanh_(s1 + bm2[1]) * 0.05f;
    }
}

// ---------------- host launcher ----------------
extern "C" void kernel_launch(void* const* d_in, const int* in_sizes, int n_in,
                              void* d_out, int out_size)
{
    const float* obs    = (const float*)d_in[0];
    const float* phys   = (const float*)d_in[1];
    const float* goals  = (const float*)d_in[2];
    const float* mem_p  = (const float*)d_in[3];
    const float* mem_a  = (const float*)d_in[4];
    const float* Wih_p  = (const float*)d_in[5];
    const float* Whh_p  = (const float*)d_in[6];
    const float* bih_p  = (const float*)d_in[7];
    const float* bhh_p  = (const float*)d_in[8];
    const float* Wfc_p  = (const float*)d_in[9];
    const float* bfc_p  = (const float*)d_in[10];
    const float* Wih_a  = (const float*)d_in[11];
    const float* Whh_a  = (const float*)d_in[12];
    const float* bih_a  = (const float*)d_in[13];
    const float* bhh_a  = (const float*)d_in[14];
    const float* Wfc_a  = (const float*)d_in[15];
    const float* bfc_a  = (const float*)d_in[16];
    const float* Wm1    = (const float*)d_in[17];
    const float* bm1    = (const float*)d_in[18];
    const float* Wm2    = (const float*)d_in[19];
    const float* bm2    = (const float*)d_in[20];
    float* out = (float*)d_out;

    void* p;
    __half *h_hi[3], *h_lo[3], *xc_hi[2], *xc_lo[2];
    cudaGetSymbolAddress(&p, g_h_hi);
    h_hi[0] = (__half*)p; h_hi[1] = h_hi[0] + (size_t)MP_ROWS*HH; h_hi[2] = h_hi[1] + (size_t)MP_ROWS*HH;
    cudaGetSymbolAddress(&p, g_h_lo);
    h_lo[0] = (__half*)p; h_lo[1] = h_lo[0] + (size_t)MP_ROWS*HH; h_lo[2] = h_lo[1] + (size_t)MP_ROWS*HH;
    cudaGetSymbolAddress(&p, g_xcat_hi); xc_hi[0] = (__half*)p; xc_hi[1] = xc_hi[0] + (size_t)MA_ROWS*512;
    cudaGetSymbolAddress(&p, g_xcat_lo); xc_lo[0] = (__half*)p; xc_lo[1] = xc_lo[0] + (size_t)MA_ROWS*512;
    cudaGetSymbolAddress(&p, g_proc_hi); __half* proc_hi = (__half*)p;
    cudaGetSymbolAddress(&p, g_t1_hi);   __half* t1_hi = (__half*)p;
    cudaGetSymbolAddress(&p, g_t2);      float* t2 = (float*)p;
    cudaGetSymbolAddress(&p, g_xp8);     float* xp8 = (float*)p;
    cudaGetSymbolAddress(&p, g_xa4);     float* xa4 = (float*)p;
    cudaGetSymbolAddress(&p, g_Wp8);     float* Wp8 = (float*)p;
    cudaGetSymbolAddress(&p, g_Wa8);     float* Wa8 = (float*)p;
    cudaGetSymbolAddress(&p, g_Whhp);    __half* Whhp = (__half*)p;
    cudaGetSymbolAddress(&p, g_Wfcp);    __half* Wfcp = (__half*)p;
    cudaGetSymbolAddress(&p, g_Wcat);    __half* Wcat = (__half*)p;
    cudaGetSymbolAddress(&p, g_Wfca);    __half* Wfca = (__half*)p;
    cudaGetSymbolAddress(&p, g_Wm1);     __half* Wm1h = (__half*)p;

    const int SM_0_128 = 3 * (128 + 192) * 72 * 2;   // 138240
    const int SM_1_64  = 3 * (64 + 256) * 72 * 2;    // 138240
    const int SM_2_128 = 3 * (128 + 64) * 72 * 2;    // 82944
    const int SM_2_64  = 3 * (64 + 64) * 72 * 2;     // 55296
    cudaFuncSetAttribute((const void*)fused_kernel<0,128>, cudaFuncAttributeMaxDynamicSharedMemorySize, SM_0_128);
    cudaFuncSetAttribute((const void*)fused_kernel<1,64>,  cudaFuncAttributeMaxDynamicSharedMemorySize, SM_1_64);
    cudaFuncSetAttribute((const void*)fused_kernel<2,128>, cudaFuncAttributeMaxDynamicSharedMemorySize, SM_2_128);
    cudaFuncSetAttribute((const void*)fused_kernel<2,64>,  cudaFuncAttributeMaxDynamicSharedMemorySize, SM_2_64);

    // ---- one-time stream/event setup (sG high-priority for the critical chain) ----
    static cudaStream_t sG = nullptr, sA = nullptr, sB = nullptr;
    static cudaEvent_t evFork = nullptr, evPrep = nullptr, evJoinA = nullptr, evJoinB = nullptr, evJoinG = nullptr;
    static cudaEvent_t evG[TT], evF[TT], evP[TT], evA[TT];
    if (sA == nullptr) {
        int prLo = 0, prHi = 0;
        cudaDeviceGetStreamPriorityRange(&prLo, &prHi);   // prHi = highest (most negative)
        cudaStreamCreateWithPriority(&sG, cudaStreamNonBlocking, prHi);
        cudaStreamCreateWithPriority(&sA, cudaStreamNonBlocking, prLo);
        cudaStreamCreateWithPriority(&sB, cudaStreamNonBlocking, prLo);
        cudaEventCreateWithFlags(&evFork, cudaEventDisableTiming);
        cudaEventCreateWithFlags(&evPrep, cudaEventDisableTiming);
        cudaEventCreateWithFlags(&evJoinA, cudaEventDisableTiming);
        cudaEventCreateWithFlags(&evJoinB, cudaEventDisableTiming);
        cudaEventCreateWithFlags(&evJoinG, cudaEventDisableTiming);
        for (int i = 0; i < TT; i++) {
            cudaEventCreateWithFlags(&evG[i], cudaEventDisableTiming);
            cudaEventCreateWithFlags(&evF[i], cudaEventDisableTiming);
            cudaEventCreateWithFlags(&evP[i], cudaEventDisableTiming);
            cudaEventCreateWithFlags(&evA[i], cudaEventDisableTiming);
        }
    }

    cudaStream_t s0 = 0;

    // ---- fork all streams off stream 0 ----
    cudaEventRecord(evFork, s0);
    cudaStreamWaitEvent(sB, evFork, 0);
    cudaStreamWaitEvent(sG, evFork, 0);
    cudaStreamWaitEvent(sA, evFork, 0);

    // ---- prep: big h-split on sG (critical); small gru_p preps on sB (overlap) ----
    split_kernel<<<(MP_ROWS*HH + 255)/256, 256, 0, sG>>>(mem_p, h_hi[0], h_lo[0], MP_ROWS*HH);
    conv_kernel<<<(G3H*HH + 255)/256, 256, 0, sB>>>(Whh_p, Whhp, G3H*HH);
    prep_xp_kernel<<<(MP_ROWS + 255)/256, 256, 0, sB>>>(obs, phys, xp8);
    prep_wp8_kernel<<<(G3H + 255)/256, 256, 0, sB>>>(Wih_p, bih_p, bhh_p, Wp8);
    cudaEventRecord(evPrep, sB);
    cudaStreamWaitEvent(sG, evPrep, 0);   // gru_p(0) needs Whhp/xp8/Wp8

    // ---- remaining prep on sB (hides under gru_p(0)) ----
    split_strided_kernel<<<(MA_ROWS*HH + 255)/256, 256, 0, sB>>>(mem_a, xc_hi[0] + 256, xc_lo[0] + 256, MA_ROWS, HH, 512);
    conv_kernel<<<(HH*HH + 255)/256, 256, 0, sB>>>(Wfc_p, Wfcp, HH*HH);
    conv_kernel<<<(HH*HH + 255)/256, 256, 0, sB>>>(Wfc_a, Wfca, HH*HH);
    conv_kernel<<<(HH*HH + 255)/256, 256, 0, sB>>>(Wm1, Wm1h, HH*HH);
    build_wcat_kernel<<<(1024*512 + 255)/256, 256, 0, sB>>>(Wih_a, Whh_a, Wcat);
    prep_xa_kernel<<<(MA_ROWS + 255)/256, 256, 0, sB>>>(goals, xa4);
    prep_wa8_kernel<<<(G3H + 255)/256, 256, 0, sB>>>(Wih_a, bih_a, bhh_a, Wa8);

    // ---- recurrence ----
    // sG (high prio): gru_p chain. sB (low): fc_p + pool. sA (low): action chain.
    // h triple-buffered: gru_p(t) reads h[t%3], writes h[(t+1)%3]; WAR -> wait evF[t-3].
    for (int t = 0; t < TT; t++) {
        int cur = t % 3;
        int nxt = (t + 1) % 3;
        int xc = t & 1, xn = (t + 1) & 1;
        // ---- physical GRU on sG ----
        if (t >= 3) cudaStreamWaitEvent(sG, evF[t - 3], 0);
        fused_kernel<0,128><<<dim3(MP_ROWS/128, 4), 256, SM_0_128, sG>>>(
            h_hi[cur], HH, Whhp, xp8, Wp8,
            h_hi[cur], h_lo[cur], HH,
            h_hi[nxt], h_lo[nxt], HH, nullptr);
        cudaEventRecord(evG[t], sG);

        // ---- fc_p + pool on sB ----
        cudaStreamWaitEvent(sB, evG[t], 0);
        fused_kernel<2,128><<<dim3(MP_ROWS/128, 4), 256, SM_2_128, sB>>>(
            h_hi[nxt], HH, Wfcp, bfc_p, nullptr,
            nullptr, nullptr, 0,
            proc_hi, nullptr, HH, nullptr);
        cudaEventRecord(evF[t], sB);
        if (t >= 2) cudaStreamWaitEvent(sB, evA[t - 2], 0);
        pool_kernel<<<(MA_ROWS*32 + 255)/256, 256, 0, sB>>>(proc_hi, xc_hi[xc]);
        cudaEventRecord(evP[t], sB);

        // ---- action chain on sA ----
        cudaStreamWaitEvent(sA, evP[t], 0);
        fused_kernel<1,64><<<dim3(MA_ROWS/64, 4), 256, SM_1_64, sA>>>(
            xc_hi[xc], 512, Wcat, xa4, Wa8,
            xc_hi[xc] + 256, xc_lo[xc] + 256, 512,
            xc_hi[xn] + 256, xc_lo[xn] + 256, 512, nullptr);
        cudaEventRecord(evA[t], sA);
        fused_kernel<2,64><<<dim3(MA_ROWS/64, 4), 256, SM_2_64, sA>>>(
            xc_hi[xn] + 256, 512, Wfca, bfc_a, nullptr,
            nullptr, nullptr, 0,
            t1_hi, nullptr, HH, nullptr);
        fused_kernel<2,64><<<dim3(MA_ROWS/64, 4), 256, SM_2_64, sA>>>(
            t1_hi, HH, Wm1h, bm1, nullptr,
            nullptr, nullptr, 0,
            nullptr, nullptr, 0, t2);
        head_kernel<<<(MA_ROWS*32 + 255)/256, 256, 0, sA>>>(t2, Wm2, bm2, out, t);
    }

    // join all streams back into stream 0
    cudaEventRecord(evJoinG, sG);
    cudaStreamWaitEvent(s0, evJoinG, 0);
    cudaEventRecord(evJoinA, sA);
    cudaStreamWaitEvent(s0, evJoinA, 0);
    cudaEventRecord(evJoinB, sB);
    cudaStreamWaitEvent(s0, evJoinB, 0);
}